// round 2
// baseline (speedup 1.0000x reference)
#include <cuda_runtime.h>
#include <math.h>

#define NN 50000
#define NE 800000
#define NODE_F 128
#define EDGE_F 32
#define TIME_D 16
#define MEM_D 128
#define K1 176            // MSG_IN
#define DN 128            // MSG_D / MEM_D

// ---------------- scratch (no allocations allowed) ----------------
__device__ float g_agg[(size_t)NN * 128];
__device__ float g_cnt[NN];

// ---------------- f32x2 packed helpers ----------------
typedef unsigned long long ull;

__device__ __forceinline__ ull pk2(float lo, float hi) {
    ull r; asm("mov.b64 %0, {%1,%2};" : "=l"(r) : "f"(lo), "f"(hi)); return r;
}
__device__ __forceinline__ ull dup2(float v) {
    ull r; asm("mov.b64 %0, {%1,%1};" : "=l"(r) : "f"(v)); return r;
}
__device__ __forceinline__ void upk2(ull p, float& lo, float& hi) {
    asm("mov.b64 {%0,%1}, %2;" : "=f"(lo), "=f"(hi) : "l"(p));
}
__device__ __forceinline__ ull ffma2(ull a, ull b, ull c) {
    ull d; asm("fma.rn.f32x2 %0, %1, %2, %3;" : "=l"(d) : "l"(a), "l"(b), "l"(c)); return d;
}

__device__ __forceinline__ float sigm(float x) { return 1.0f / (1.0f + expf(-x)); }

// ---------------- zero scratch ----------------
__global__ void zero_kernel() {
    int i = blockIdx.x * blockDim.x + threadIdx.x;
    int stride = gridDim.x * blockDim.x;
    float4 z = make_float4(0.f, 0.f, 0.f, 0.f);
    float4* a4 = reinterpret_cast<float4*>(g_agg);
    for (int j = i; j < NN * 128 / 4; j += stride) a4[j] = z;
    for (int j = i; j < NN; j += stride) g_cnt[j] = 0.f;
}

// ---------------- generic 3m x 8n f32x2 micro-GEMM (B stride = 128) ----------------
template<int K>
__device__ __forceinline__ void gemm3x8(const float* __restrict__ A0,
                                        const float* __restrict__ A1,
                                        const float* __restrict__ A2,
                                        const float* __restrict__ Bs,
                                        int n0, ull acc[3][4]) {
#pragma unroll 4
    for (int k = 0; k < K; ++k) {
        ull a0 = dup2(A0[k]);
        ull a1 = dup2(A1[k]);
        ull a2 = dup2(A2[k]);
        float4 bA = *(const float4*)&Bs[k * 128 + n0];
        float4 bB = *(const float4*)&Bs[k * 128 + n0 + 4];
        ull db0 = pk2(bA.x, bA.y), db1 = pk2(bA.z, bA.w);
        ull db2 = pk2(bB.x, bB.y), db3 = pk2(bB.z, bB.w);
        acc[0][0] = ffma2(a0, db0, acc[0][0]); acc[0][1] = ffma2(a0, db1, acc[0][1]);
        acc[0][2] = ffma2(a0, db2, acc[0][2]); acc[0][3] = ffma2(a0, db3, acc[0][3]);
        acc[1][0] = ffma2(a1, db0, acc[1][0]); acc[1][1] = ffma2(a1, db1, acc[1][1]);
        acc[1][2] = ffma2(a1, db2, acc[1][2]); acc[1][3] = ffma2(a1, db3, acc[1][3]);
        acc[2][0] = ffma2(a2, db0, acc[2][0]); acc[2][1] = ffma2(a2, db1, acc[2][1]);
        acc[2][2] = ffma2(a2, db2, acc[2][2]); acc[2][3] = ffma2(a2, db3, acc[2][3]);
    }
}

// ---------------- edge kernel: fused time-enc + gather + MLP + scatter ----------------
#define EK_BM 48
#define EK_AS 180          // A tile stride (pad for conflict-free scalar reads)
#define EK_HS 132          // H tile stride

// smem (floats): W1 22528 | W2 16384 | A 48*180=8640 | H 48*132=6336 | tgt 48 ints
#define EDGE_SMEM_FLOATS (22528 + 16384 + 8640 + 6336)
#define EDGE_SMEM_BYTES  (EDGE_SMEM_FLOATS * 4 + EK_BM * 4)

__global__ __launch_bounds__(256, 1)
void edge_kernel(const float* __restrict__ x, const float* __restrict__ eattr,
                 const float* __restrict__ tt, const float* __restrict__ tw,
                 const float* __restrict__ tb, const float* __restrict__ w1,
                 const float* __restrict__ b1, const float* __restrict__ w2,
                 const float* __restrict__ b2, const int* __restrict__ ei)
{
    extern __shared__ float sm[];
    float* W1s = sm;                     // [176][128]
    float* W2s = W1s + 22528;            // [128][128]
    float* As  = W2s + 16384;            // [48][180]
    float* Hs  = As + 8640;              // [48][132]
    int*   tgts = (int*)(Hs + 6336);     // [48]

    const int tid = threadIdx.x;

    for (int i = tid; i < K1 * DN; i += 256) W1s[i] = w1[i];
    for (int i = tid; i < DN * DN; i += 256) W2s[i] = w2[i];

    const int tn = tid & 15, tm = tid >> 4;
    const int m0 = tm * 3, n0 = tn * 8;

    ull bb1[4], bb2[4];
#pragma unroll
    for (int j = 0; j < 4; ++j) {
        bb1[j] = pk2(__ldg(&b1[n0 + 2 * j]), __ldg(&b1[n0 + 2 * j + 1]));
        bb2[j] = pk2(__ldg(&b2[n0 + 2 * j]), __ldg(&b2[n0 + 2 * j + 1]));
    }

    const int ntiles = (NE + EK_BM - 1) / EK_BM;
    for (int tile = blockIdx.x; tile < ntiles; tile += gridDim.x) {
        __syncthreads();   // prev tile fully consumed (also covers weight-load on iter 0)

        const int ebase = tile * EK_BM;
        // ---- build A tile: [x[src] | edge_attr | cos(t*w+b)] ----
        for (int idx = tid; idx < EK_BM * K1; idx += 256) {
            int e = idx / K1;
            int f = idx - e * K1;
            int ge = ebase + e;
            float v = 0.f;
            if (ge < NE) {
                if (f < NODE_F) {
                    int s = __ldg(&ei[ge]);
                    v = __ldg(&x[s * NODE_F + f]);
                } else if (f < NODE_F + EDGE_F) {
                    v = __ldg(&eattr[ge * EDGE_F + (f - NODE_F)]);
                } else {
                    int d = f - NODE_F - EDGE_F;
                    v = cosf(__ldg(&tt[ge]) * __ldg(&tw[d]) + __ldg(&tb[d]));
                }
            }
            As[e * EK_AS + f] = v;
            if (f == 0) {
                int tg = -1;
                if (ge < NE) {
                    tg = __ldg(&ei[NE + ge]);
                    atomicAdd(&g_cnt[tg], 1.0f);
                }
                tgts[e] = tg;
            }
        }
        __syncthreads();

        // ---- GEMM1: h1 = relu(A @ W1 + b1) ----
        ull acc[3][4];
#pragma unroll
        for (int i = 0; i < 3; ++i)
#pragma unroll
            for (int j = 0; j < 4; ++j) acc[i][j] = bb1[j];

        gemm3x8<K1>(&As[(m0 + 0) * EK_AS], &As[(m0 + 1) * EK_AS], &As[(m0 + 2) * EK_AS],
                    W1s, n0, acc);

#pragma unroll
        for (int i = 0; i < 3; ++i) {
            float h[8];
            upk2(acc[i][0], h[0], h[1]); upk2(acc[i][1], h[2], h[3]);
            upk2(acc[i][2], h[4], h[5]); upk2(acc[i][3], h[6], h[7]);
#pragma unroll
            for (int u = 0; u < 8; ++u) h[u] = fmaxf(h[u], 0.f);
            float4* dst = (float4*)&Hs[(m0 + i) * EK_HS + n0];
            dst[0] = make_float4(h[0], h[1], h[2], h[3]);
            dst[1] = make_float4(h[4], h[5], h[6], h[7]);
        }
        __syncthreads();

        // ---- GEMM2: msg = h1 @ W2 + b2 ----
#pragma unroll
        for (int i = 0; i < 3; ++i)
#pragma unroll
            for (int j = 0; j < 4; ++j) acc[i][j] = bb2[j];

        gemm3x8<DN>(&Hs[(m0 + 0) * EK_HS], &Hs[(m0 + 1) * EK_HS], &Hs[(m0 + 2) * EK_HS],
                    W2s, n0, acc);

        // ---- scatter: vector reduction into g_agg[tgt] ----
#pragma unroll
        for (int i = 0; i < 3; ++i) {
            int tg = tgts[m0 + i];
            if (tg >= 0) {
                float o[8];
                upk2(acc[i][0], o[0], o[1]); upk2(acc[i][1], o[2], o[3]);
                upk2(acc[i][2], o[4], o[5]); upk2(acc[i][3], o[6], o[7]);
                size_t ga = __cvta_generic_to_global(&g_agg[(size_t)tg * 128 + n0]);
                asm volatile("red.global.add.v4.f32 [%0], {%1,%2,%3,%4};"
                             :: "l"(ga), "f"(o[0]), "f"(o[1]), "f"(o[2]), "f"(o[3]) : "memory");
                asm volatile("red.global.add.v4.f32 [%0], {%1,%2,%3,%4};"
                             :: "l"(ga + 16), "f"(o[4]), "f"(o[5]), "f"(o[6]), "f"(o[7]) : "memory");
            }
        }
    }
}

// ---------------- node kernel: mean + GRU (h0=0) + out projection ----------------
#define NK_BM 64
// smem floats: Vs 64*132 | Ws 128*132 | Ms 64*132
#define NODE_SMEM_BYTES ((8448 + 16896 + 8448) * 4)

__device__ __forceinline__ void stage_wT(const float* __restrict__ src, float* Ws, int tid) {
    for (int idx = tid; idx < 128 * 128; idx += 256) {
        int j = idx >> 7, k = idx & 127;
        Ws[k * 132 + j] = __ldg(&src[j * 128 + k]);
    }
}

__device__ __forceinline__ void gemm4x8_s132(const float* __restrict__ A0,
                                             const float* __restrict__ A1,
                                             const float* __restrict__ A2,
                                             const float* __restrict__ A3,
                                             const float* __restrict__ Ws,
                                             int n0, ull acc[4][4]) {
#pragma unroll 4
    for (int k = 0; k < 128; ++k) {
        ull a0 = dup2(A0[k]), a1 = dup2(A1[k]), a2 = dup2(A2[k]), a3 = dup2(A3[k]);
        float4 bA = *(const float4*)&Ws[k * 132 + n0];
        float4 bB = *(const float4*)&Ws[k * 132 + n0 + 4];
        ull db0 = pk2(bA.x, bA.y), db1 = pk2(bA.z, bA.w);
        ull db2 = pk2(bB.x, bB.y), db3 = pk2(bB.z, bB.w);
        acc[0][0] = ffma2(a0, db0, acc[0][0]); acc[0][1] = ffma2(a0, db1, acc[0][1]);
        acc[0][2] = ffma2(a0, db2, acc[0][2]); acc[0][3] = ffma2(a0, db3, acc[0][3]);
        acc[1][0] = ffma2(a1, db0, acc[1][0]); acc[1][1] = ffma2(a1, db1, acc[1][1]);
        acc[1][2] = ffma2(a1, db2, acc[1][2]); acc[1][3] = ffma2(a1, db3, acc[1][3]);
        acc[2][0] = ffma2(a2, db0, acc[2][0]); acc[2][1] = ffma2(a2, db1, acc[2][1]);
        acc[2][2] = ffma2(a2, db2, acc[2][2]); acc[2][3] = ffma2(a2, db3, acc[2][3]);
        acc[3][0] = ffma2(a3, db0, acc[3][0]); acc[3][1] = ffma2(a3, db1, acc[3][1]);
        acc[3][2] = ffma2(a3, db2, acc[3][2]); acc[3][3] = ffma2(a3, db3, acc[3][3]);
    }
}

__global__ __launch_bounds__(256, 1)
void node_kernel(const float* __restrict__ wih, const float* __restrict__ bih,
                 const float* __restrict__ bhh, const float* __restrict__ ow,
                 const float* __restrict__ ob, float* __restrict__ out)
{
    extern __shared__ float sm[];
    float* Vs = sm;                 // [64][132]
    float* Ws = Vs + 8448;          // [128][132] transposed weight chunk
    float* Ms = Ws + 16896;         // [64][132] memory

    const int tid = threadIdx.x;
    const int base = blockIdx.x * NK_BM;

    // mean-aggregated input
    for (int idx = tid; idx < NK_BM * 128; idx += 256) {
        int m = idx >> 7, f = idx & 127;
        int nd = base + m;
        float v = 0.f;
        if (nd < NN) v = g_agg[(size_t)nd * 128 + f] / fmaxf(g_cnt[nd], 1.0f);
        Vs[m * 132 + f] = v;
    }

    const int tn = tid & 15, tm = tid >> 4;
    const int m0 = tm * 4, n0 = tn * 8;

    const float* V0 = &Vs[(m0 + 0) * 132];
    const float* V1 = &Vs[(m0 + 1) * 132];
    const float* V2 = &Vs[(m0 + 2) * 132];
    const float* V3 = &Vs[(m0 + 3) * 132];

    ull acc[4][4];
    float rg[4][8];    // r gate
    float ng[4][8];    // n gate

    // ---- r gate (rows [0,128) of W_ih) ----
    stage_wT(wih, Ws, tid);
    __syncthreads();
#pragma unroll
    for (int i = 0; i < 4; ++i)
#pragma unroll
        for (int j = 0; j < 4; ++j) acc[i][j] = 0ull;
    gemm4x8_s132(V0, V1, V2, V3, Ws, n0, acc);
#pragma unroll
    for (int i = 0; i < 4; ++i) {
        float v[8];
        upk2(acc[i][0], v[0], v[1]); upk2(acc[i][1], v[2], v[3]);
        upk2(acc[i][2], v[4], v[5]); upk2(acc[i][3], v[6], v[7]);
#pragma unroll
        for (int u = 0; u < 8; ++u) {
            int n = n0 + u;
            rg[i][u] = sigm(v[u] + __ldg(&bih[n]) + __ldg(&bhh[n]));
        }
    }
    __syncthreads();

    // ---- n gate (rows [256,384)) : n = tanh(i_n + r * b_hh_n) ----
    stage_wT(wih + 2 * 128 * 128, Ws, tid);
    __syncthreads();
#pragma unroll
    for (int i = 0; i < 4; ++i)
#pragma unroll
        for (int j = 0; j < 4; ++j) acc[i][j] = 0ull;
    gemm4x8_s132(V0, V1, V2, V3, Ws, n0, acc);
#pragma unroll
    for (int i = 0; i < 4; ++i) {
        float v[8];
        upk2(acc[i][0], v[0], v[1]); upk2(acc[i][1], v[2], v[3]);
        upk2(acc[i][2], v[4], v[5]); upk2(acc[i][3], v[6], v[7]);
#pragma unroll
        for (int u = 0; u < 8; ++u) {
            int n = 256 + n0 + u;
            ng[i][u] = tanhf(v[u] + __ldg(&bih[n]) + rg[i][u] * __ldg(&bhh[n]));
        }
    }
    __syncthreads();

    // ---- z gate (rows [128,256)) + memory = (1-z)*n ----
    stage_wT(wih + 1 * 128 * 128, Ws, tid);
    __syncthreads();
#pragma unroll
    for (int i = 0; i < 4; ++i)
#pragma unroll
        for (int j = 0; j < 4; ++j) acc[i][j] = 0ull;
    gemm4x8_s132(V0, V1, V2, V3, Ws, n0, acc);
#pragma unroll
    for (int i = 0; i < 4; ++i) {
        float v[8];
        upk2(acc[i][0], v[0], v[1]); upk2(acc[i][1], v[2], v[3]);
        upk2(acc[i][2], v[4], v[5]); upk2(acc[i][3], v[6], v[7]);
        float mvals[8];
#pragma unroll
        for (int u = 0; u < 8; ++u) {
            int n = 128 + n0 + u;
            float z = sigm(v[u] + __ldg(&bih[n]) + __ldg(&bhh[n]));
            mvals[u] = (1.0f - z) * ng[i][u];
        }
        float4* dst = (float4*)&Ms[(m0 + i) * 132 + n0];
        dst[0] = make_float4(mvals[0], mvals[1], mvals[2], mvals[3]);
        dst[1] = make_float4(mvals[4], mvals[5], mvals[6], mvals[7]);
    }
    __syncthreads();

    // ---- out = memory @ out_w^T + out_b ----
    stage_wT(ow, Ws, tid);
    __syncthreads();
#pragma unroll
    for (int i = 0; i < 4; ++i)
#pragma unroll
        for (int j = 0; j < 4; ++j) acc[i][j] = 0ull;
    gemm4x8_s132(&Ms[(m0 + 0) * 132], &Ms[(m0 + 1) * 132],
                 &Ms[(m0 + 2) * 132], &Ms[(m0 + 3) * 132], Ws, n0, acc);
#pragma unroll
    for (int i = 0; i < 4; ++i) {
        int nd = base + m0 + i;
        if (nd < NN) {
            float v[8];
            upk2(acc[i][0], v[0], v[1]); upk2(acc[i][1], v[2], v[3]);
            upk2(acc[i][2], v[4], v[5]); upk2(acc[i][3], v[6], v[7]);
#pragma unroll
            for (int u = 0; u < 8; ++u) v[u] += __ldg(&ob[n0 + u]);
            float4* dst = (float4*)&out[(size_t)nd * 128 + n0];
            dst[0] = make_float4(v[0], v[1], v[2], v[3]);
            dst[1] = make_float4(v[4], v[5], v[6], v[7]);
        }
    }
}

// ---------------- launch ----------------
extern "C" void kernel_launch(void* const* d_in, const int* in_sizes, int n_in,
                              void* d_out, int out_size) {
    const float* x     = (const float*)d_in[0];
    const float* eattr = (const float*)d_in[1];
    const float* t     = (const float*)d_in[2];
    const float* tw    = (const float*)d_in[3];
    const float* tb    = (const float*)d_in[4];
    const float* w1    = (const float*)d_in[5];
    const float* b1    = (const float*)d_in[6];
    const float* w2    = (const float*)d_in[7];
    const float* b2    = (const float*)d_in[8];
    const float* wih   = (const float*)d_in[9];
    // d_in[10] = gru_w_hh: unused (h0 == 0)
    const float* bih   = (const float*)d_in[11];
    const float* bhh   = (const float*)d_in[12];
    const float* ow    = (const float*)d_in[13];
    const float* ob    = (const float*)d_in[14];
    const int*   ei    = (const int*)d_in[15];
    float* out = (float*)d_out;

    cudaFuncSetAttribute(edge_kernel, cudaFuncAttributeMaxDynamicSharedMemorySize, EDGE_SMEM_BYTES);
    cudaFuncSetAttribute(node_kernel, cudaFuncAttributeMaxDynamicSharedMemorySize, NODE_SMEM_BYTES);

    zero_kernel<<<256, 256>>>();
    edge_kernel<<<148, 256, EDGE_SMEM_BYTES>>>(x, eattr, t, tw, tb, w1, b1, w2, b2, ei);
    node_kernel<<<(NN + NK_BM - 1) / NK_BM, 256, NODE_SMEM_BYTES>>>(wih, bih, bhh, ow, ob, out);
}

// round 4
// speedup vs baseline: 2.7729x; 2.7729x over previous
#include <cuda_runtime.h>
#include <cuda_bf16.h>
#include <math.h>
#include <stdint.h>

#define NN 50000
#define NE 800000
#define NODE_F 128
#define EDGE_F 32
#define TIME_D 16
#define K1 176
#define DN 128

typedef unsigned long long ull;

// ---------------- scratch ----------------
__device__ float g_agg[(size_t)NN * 128];
__device__ float g_cnt[NN];

// ---------------- helpers ----------------
__device__ __forceinline__ uint32_t smem_u32(const void* p) {
    uint32_t a;
    asm("{ .reg .u64 t; cvta.to.shared.u64 t, %1; cvt.u32.u64 %0, t; }" : "=r"(a) : "l"(p));
    return a;
}
__device__ __forceinline__ ull pk2(float lo, float hi) {
    ull r; asm("mov.b64 %0, {%1,%2};" : "=l"(r) : "f"(lo), "f"(hi)); return r;
}
__device__ __forceinline__ ull dup2(float v) {
    ull r; asm("mov.b64 %0, {%1,%1};" : "=l"(r) : "f"(v)); return r;
}
__device__ __forceinline__ void upk2(ull p, float& lo, float& hi) {
    asm("mov.b64 {%0,%1}, %2;" : "=f"(lo), "=f"(hi) : "l"(p));
}
__device__ __forceinline__ ull ffma2(ull a, ull b, ull c) {
    ull d; asm("fma.rn.f32x2 %0, %1, %2, %3;" : "=l"(d) : "l"(a), "l"(b), "l"(c)); return d;
}
__device__ __forceinline__ float sigm(float x) { return 1.0f / (1.0f + expf(-x)); }

__device__ __forceinline__ void split1(float v, __nv_bfloat16& h, __nv_bfloat16& l) {
    h = __float2bfloat16(v);
    l = __float2bfloat16(v - __bfloat162float(h));
}

__device__ __forceinline__ void ldsm_x4(uint32_t& r0, uint32_t& r1, uint32_t& r2, uint32_t& r3,
                                        uint32_t addr) {
    asm volatile("ldmatrix.sync.aligned.m8n8.x4.shared.b16 {%0,%1,%2,%3}, [%4];"
                 : "=r"(r0), "=r"(r1), "=r"(r2), "=r"(r3) : "r"(addr));
}
__device__ __forceinline__ void mma_bf16(float* d, const uint32_t* a, const uint32_t* b) {
    asm volatile("mma.sync.aligned.m16n8k16.row.col.f32.bf16.bf16.f32 "
                 "{%0,%1,%2,%3}, {%4,%5,%6,%7}, {%8,%9}, {%0,%1,%2,%3};"
                 : "+f"(d[0]), "+f"(d[1]), "+f"(d[2]), "+f"(d[3])
                 : "r"(a[0]), "r"(a[1]), "r"(a[2]), "r"(a[3]), "r"(b[0]), "r"(b[1]));
}

// ---------------- zero scratch ----------------
__global__ void zero_kernel() {
    int i = blockIdx.x * blockDim.x + threadIdx.x;
    int stride = gridDim.x * blockDim.x;
    float4 z = make_float4(0.f, 0.f, 0.f, 0.f);
    float4* a4 = reinterpret_cast<float4*>(g_agg);
    for (int j = i; j < NN * 128 / 4; j += stride) a4[j] = z;
    for (int j = i; j < NN; j += stride) g_cnt[j] = 0.f;
}

// ================= EDGE KERNEL (mma.sync bf16x3) =================
#define EK_M   64          // edges per tile
#define LDA    184         // A / W1 stride (bf16 elems)
#define LDH    136         // H / W2 stride

// smem byte offsets
#define SM_A_HI   0                       // 64*184*2 = 23552 (overlaid by H after GEMM1)
#define SM_A_LO   23552                   // 23552
#define SM_H_HI   0                       // 64*136*2 = 17408 (overlay)
#define SM_H_LO   23552
#define SM_W1_HI  47104                   // 128*184*2 = 47104
#define SM_W1_LO  94208
#define SM_W2_HI  141312                  // 128*136*2 = 34816
#define SM_W2_LO  176128
#define SM_B1     210944                  // 128 floats
#define SM_B2     211456
#define SM_TGT    211968                  // 64 ints
#define EDGE_SMEM_BYTES 212224

__global__ __launch_bounds__(256, 1)
void edge_kernel(const float* __restrict__ x, const float* __restrict__ eattr,
                 const float* __restrict__ tt, const float* __restrict__ tw,
                 const float* __restrict__ tb, const float* __restrict__ w1,
                 const float* __restrict__ b1, const float* __restrict__ w2,
                 const float* __restrict__ b2, const int* __restrict__ ei)
{
    extern __shared__ char smc[];
    const uint32_t smb = smem_u32(smc);
    const int tid = threadIdx.x;
    const int wid = tid >> 5, lane = tid & 31;
    const int wm = wid & 3, wn = wid >> 2;       // warp grid: 4 m-warps x 2 n-halves
    const int m0 = wm * 16;                       // warp's row base
    const int nbase = wn * 64;                    // warp's col base

    float* b1s = (float*)(smc + SM_B1);
    float* b2s = (float*)(smc + SM_B2);
    int*   tgts = (int*)(smc + SM_TGT);

    // ---- stage weights: transpose to [n][k], hi/lo bf16 split ----
    for (int idx = tid; idx < K1 * DN; idx += 256) {
        int k = idx >> 7, n = idx & 127;
        __nv_bfloat16 h, l;
        split1(w1[idx], h, l);
        *(__nv_bfloat16*)(smc + SM_W1_HI + 2 * (n * LDA + k)) = h;
        *(__nv_bfloat16*)(smc + SM_W1_LO + 2 * (n * LDA + k)) = l;
    }
    for (int idx = tid; idx < DN * DN; idx += 256) {
        int k = idx >> 7, n = idx & 127;
        __nv_bfloat16 h, l;
        split1(w2[idx], h, l);
        *(__nv_bfloat16*)(smc + SM_W2_HI + 2 * (n * LDH + k)) = h;
        *(__nv_bfloat16*)(smc + SM_W2_LO + 2 * (n * LDH + k)) = l;
    }
    for (int i = tid; i < 128; i += 256) { b1s[i] = b1[i]; b2s[i] = b2[i]; }

    // fragment lane addressing (bytes), invariant parts
    // A frag: row = m0 + (lane&15), col piece = (lane>>4)*8
    const uint32_t aRowOff = (uint32_t)((m0 + (lane & 15)) * LDA + ((lane >> 4) << 3)) * 2;
    const uint32_t hRowOff = (uint32_t)((m0 + (lane & 15)) * LDH + ((lane >> 4) << 3)) * 2;
    // B frag (x4 = 2 n-chunks): row = n + (lane&7) + (lane>>4)*8 ; col piece = ((lane>>3)&1)*8
    const uint32_t bRow = (uint32_t)((lane & 7) + ((lane >> 4) << 3));
    const uint32_t bColPiece = (uint32_t)(((lane >> 3) & 1) << 3);
    const uint32_t b1LaneOff = (uint32_t)(bRow * LDA + bColPiece) * 2;
    const uint32_t b2LaneOff = (uint32_t)(bRow * LDH + bColPiece) * 2;

    const int crow = lane >> 2;          // c-frag row within m16 (and +8)
    const int ccol = (lane & 3) * 2;     // c-frag col pair within n8

    for (int tile = blockIdx.x; tile < NE / EK_M; tile += gridDim.x) {
        __syncthreads();   // previous tile fully consumed (H reads done)

        const int ebase = tile * EK_M;

        // ---------- build A tile (hi/lo) ----------
        for (int idx = tid; idx < EK_M * 128; idx += 256) {      // x[src]
            int e = idx >> 7, f = idx & 127;
            int src = __ldg(&ei[ebase + e]);
            __nv_bfloat16 h, l;
            split1(__ldg(&x[(size_t)src * 128 + f]), h, l);
            *(__nv_bfloat16*)(smc + SM_A_HI + 2 * (e * LDA + f)) = h;
            *(__nv_bfloat16*)(smc + SM_A_LO + 2 * (e * LDA + f)) = l;
        }
        for (int idx = tid; idx < EK_M * 32; idx += 256) {       // edge_attr
            int e = idx >> 5, f = idx & 31;
            __nv_bfloat16 h, l;
            split1(__ldg(&eattr[(size_t)(ebase + e) * 32 + f]), h, l);
            *(__nv_bfloat16*)(smc + SM_A_HI + 2 * (e * LDA + 128 + f)) = h;
            *(__nv_bfloat16*)(smc + SM_A_LO + 2 * (e * LDA + 128 + f)) = l;
        }
        for (int idx = tid; idx < EK_M * 16; idx += 256) {       // time enc
            int e = idx >> 4, d = idx & 15;
            float v = cosf(__ldg(&tt[ebase + e]) * __ldg(&tw[d]) + __ldg(&tb[d]));
            __nv_bfloat16 h, l;
            split1(v, h, l);
            *(__nv_bfloat16*)(smc + SM_A_HI + 2 * (e * LDA + 160 + d)) = h;
            *(__nv_bfloat16*)(smc + SM_A_LO + 2 * (e * LDA + 160 + d)) = l;
        }
        if (tid < EK_M) {
            int tg = __ldg(&ei[NE + ebase + tid]);
            tgts[tid] = tg;
            atomicAdd(&g_cnt[tg], 1.0f);
        }
        __syncthreads();

        // ---------- GEMM1: D1 = A(176) @ W1, bf16x3 ----------
        float acc[8][4];
#pragma unroll
        for (int j = 0; j < 8; ++j)
#pragma unroll
            for (int q = 0; q < 4; ++q) acc[j][q] = 0.f;

        for (int ks = 0; ks < 11; ++ks) {
            const uint32_t kOff = (uint32_t)(ks * 16) * 2;
            uint32_t ah[4], al[4];
            ldsm_x4(ah[0], ah[1], ah[2], ah[3], smb + SM_A_HI + aRowOff + kOff);
            ldsm_x4(al[0], al[1], al[2], al[3], smb + SM_A_LO + aRowOff + kOff);
#pragma unroll
            for (int jj = 0; jj < 4; ++jj) {
                const uint32_t nOff = (uint32_t)((nbase + jj * 16) * LDA) * 2;
                uint32_t bh[4], bl[4];
                ldsm_x4(bh[0], bh[1], bh[2], bh[3], smb + SM_W1_HI + b1LaneOff + nOff + kOff);
                ldsm_x4(bl[0], bl[1], bl[2], bl[3], smb + SM_W1_LO + b1LaneOff + nOff + kOff);
                mma_bf16(acc[2 * jj],     ah, bh);
                mma_bf16(acc[2 * jj + 1], ah, bh + 2);
                mma_bf16(acc[2 * jj],     ah, bl);
                mma_bf16(acc[2 * jj + 1], ah, bl + 2);
                mma_bf16(acc[2 * jj],     al, bh);
                mma_bf16(acc[2 * jj + 1], al, bh + 2);
            }
        }
        __syncthreads();   // all warps done reading A before H overlay write

        // ---------- epilogue 1: relu(D1 + b1) -> H (hi/lo bf16) ----------
#pragma unroll
        for (int j = 0; j < 8; ++j) {
            int n = nbase + j * 8 + ccol;
            float v0 = fmaxf(acc[j][0] + b1s[n],     0.f);
            float v1 = fmaxf(acc[j][1] + b1s[n + 1], 0.f);
            float v2 = fmaxf(acc[j][2] + b1s[n],     0.f);
            float v3 = fmaxf(acc[j][3] + b1s[n + 1], 0.f);
            __nv_bfloat162 h01, l01, h23, l23;
            split1(v0, h01.x, l01.x); split1(v1, h01.y, l01.y);
            split1(v2, h23.x, l23.x); split1(v3, h23.y, l23.y);
            int r0 = m0 + crow, r1 = m0 + crow + 8;
            *(__nv_bfloat162*)(smc + SM_H_HI + 2 * (r0 * LDH + n)) = h01;
            *(__nv_bfloat162*)(smc + SM_H_LO + 2 * (r0 * LDH + n)) = l01;
            *(__nv_bfloat162*)(smc + SM_H_HI + 2 * (r1 * LDH + n)) = h23;
            *(__nv_bfloat162*)(smc + SM_H_LO + 2 * (r1 * LDH + n)) = l23;
        }
        __syncthreads();

        // ---------- GEMM2: D2 = H(128) @ W2, bf16x3 ----------
#pragma unroll
        for (int j = 0; j < 8; ++j)
#pragma unroll
            for (int q = 0; q < 4; ++q) acc[j][q] = 0.f;

        for (int ks = 0; ks < 8; ++ks) {
            const uint32_t kOff = (uint32_t)(ks * 16) * 2;
            uint32_t ah[4], al[4];
            ldsm_x4(ah[0], ah[1], ah[2], ah[3], smb + SM_H_HI + hRowOff + kOff);
            ldsm_x4(al[0], al[1], al[2], al[3], smb + SM_H_LO + hRowOff + kOff);
#pragma unroll
            for (int jj = 0; jj < 4; ++jj) {
                const uint32_t nOff = (uint32_t)((nbase + jj * 16) * LDH) * 2;
                uint32_t bh[4], bl[4];
                ldsm_x4(bh[0], bh[1], bh[2], bh[3], smb + SM_W2_HI + b2LaneOff + nOff + kOff);
                ldsm_x4(bl[0], bl[1], bl[2], bl[3], smb + SM_W2_LO + b2LaneOff + nOff + kOff);
                mma_bf16(acc[2 * jj],     ah, bh);
                mma_bf16(acc[2 * jj + 1], ah, bh + 2);
                mma_bf16(acc[2 * jj],     ah, bl);
                mma_bf16(acc[2 * jj + 1], ah, bl + 2);
                mma_bf16(acc[2 * jj],     al, bh);
                mma_bf16(acc[2 * jj + 1], al, bh + 2);
            }
        }

        // ---------- epilogue 2: scatter D2 + b2 into g_agg ----------
        {
            int tg0 = tgts[m0 + crow];
            int tg1 = tgts[m0 + crow + 8];
            size_t ga0 = __cvta_generic_to_global(&g_agg[(size_t)tg0 * 128]);
            size_t ga1 = __cvta_generic_to_global(&g_agg[(size_t)tg1 * 128]);
#pragma unroll
            for (int j = 0; j < 8; ++j) {
                int n = nbase + j * 8 + ccol;
                float v0 = acc[j][0] + b2s[n];
                float v1 = acc[j][1] + b2s[n + 1];
                float v2 = acc[j][2] + b2s[n];
                float v3 = acc[j][3] + b2s[n + 1];
                asm volatile("red.global.add.v2.f32 [%0], {%1,%2};"
                             :: "l"(ga0 + (size_t)n * 4), "f"(v0), "f"(v1) : "memory");
                asm volatile("red.global.add.v2.f32 [%0], {%1,%2};"
                             :: "l"(ga1 + (size_t)n * 4), "f"(v2), "f"(v3) : "memory");
            }
        }
    }
}

// ================= NODE KERNEL (unchanged, passing R2 version) =================
#define NK_BM 64
#define NODE_SMEM_BYTES ((8448 + 16896 + 8448) * 4)

__device__ __forceinline__ void stage_wT(const float* __restrict__ src, float* Ws, int tid) {
    for (int idx = tid; idx < 128 * 128; idx += 256) {
        int j = idx >> 7, k = idx & 127;
        Ws[k * 132 + j] = __ldg(&src[j * 128 + k]);
    }
}

__device__ __forceinline__ void gemm4x8_s132(const float* __restrict__ A0,
                                             const float* __restrict__ A1,
                                             const float* __restrict__ A2,
                                             const float* __restrict__ A3,
                                             const float* __restrict__ Ws,
                                             int n0, ull acc[4][4]) {
#pragma unroll 4
    for (int k = 0; k < 128; ++k) {
        ull a0 = dup2(A0[k]), a1 = dup2(A1[k]), a2 = dup2(A2[k]), a3 = dup2(A3[k]);
        float4 bA = *(const float4*)&Ws[k * 132 + n0];
        float4 bB = *(const float4*)&Ws[k * 132 + n0 + 4];
        ull db0 = pk2(bA.x, bA.y), db1 = pk2(bA.z, bA.w);
        ull db2 = pk2(bB.x, bB.y), db3 = pk2(bB.z, bB.w);
        acc[0][0] = ffma2(a0, db0, acc[0][0]); acc[0][1] = ffma2(a0, db1, acc[0][1]);
        acc[0][2] = ffma2(a0, db2, acc[0][2]); acc[0][3] = ffma2(a0, db3, acc[0][3]);
        acc[1][0] = ffma2(a1, db0, acc[1][0]); acc[1][1] = ffma2(a1, db1, acc[1][1]);
        acc[1][2] = ffma2(a1, db2, acc[1][2]); acc[1][3] = ffma2(a1, db3, acc[1][3]);
        acc[2][0] = ffma2(a2, db0, acc[2][0]); acc[2][1] = ffma2(a2, db1, acc[2][1]);
        acc[2][2] = ffma2(a2, db2, acc[2][2]); acc[2][3] = ffma2(a2, db3, acc[2][3]);
        acc[3][0] = ffma2(a3, db0, acc[3][0]); acc[3][1] = ffma2(a3, db1, acc[3][1]);
        acc[3][2] = ffma2(a3, db2, acc[3][2]); acc[3][3] = ffma2(a3, db3, acc[3][3]);
    }
}

__global__ __launch_bounds__(256, 1)
void node_kernel(const float* __restrict__ wih, const float* __restrict__ bih,
                 const float* __restrict__ bhh, const float* __restrict__ ow,
                 const float* __restrict__ ob, float* __restrict__ out)
{
    extern __shared__ float sm[];
    float* Vs = sm;
    float* Ws = Vs + 8448;
    float* Ms = Ws + 16896;

    const int tid = threadIdx.x;
    const int base = blockIdx.x * NK_BM;

    for (int idx = tid; idx < NK_BM * 128; idx += 256) {
        int m = idx >> 7, f = idx & 127;
        int nd = base + m;
        float v = 0.f;
        if (nd < NN) v = g_agg[(size_t)nd * 128 + f] / fmaxf(g_cnt[nd], 1.0f);
        Vs[m * 132 + f] = v;
    }

    const int tn = tid & 15, tm0 = tid >> 4;
    const int m0 = tm0 * 4, n0 = tn * 8;

    const float* V0 = &Vs[(m0 + 0) * 132];
    const float* V1 = &Vs[(m0 + 1) * 132];
    const float* V2 = &Vs[(m0 + 2) * 132];
    const float* V3 = &Vs[(m0 + 3) * 132];

    ull acc[4][4];
    float rg[4][8];
    float ng[4][8];

    stage_wT(wih, Ws, tid);
    __syncthreads();
#pragma unroll
    for (int i = 0; i < 4; ++i)
#pragma unroll
        for (int j = 0; j < 4; ++j) acc[i][j] = 0ull;
    gemm4x8_s132(V0, V1, V2, V3, Ws, n0, acc);
#pragma unroll
    for (int i = 0; i < 4; ++i) {
        float v[8];
        upk2(acc[i][0], v[0], v[1]); upk2(acc[i][1], v[2], v[3]);
        upk2(acc[i][2], v[4], v[5]); upk2(acc[i][3], v[6], v[7]);
#pragma unroll
        for (int u = 0; u < 8; ++u) {
            int n = n0 + u;
            rg[i][u] = sigm(v[u] + __ldg(&bih[n]) + __ldg(&bhh[n]));
        }
    }
    __syncthreads();

    stage_wT(wih + 2 * 128 * 128, Ws, tid);
    __syncthreads();
#pragma unroll
    for (int i = 0; i < 4; ++i)
#pragma unroll
        for (int j = 0; j < 4; ++j) acc[i][j] = 0ull;
    gemm4x8_s132(V0, V1, V2, V3, Ws, n0, acc);
#pragma unroll
    for (int i = 0; i < 4; ++i) {
        float v[8];
        upk2(acc[i][0], v[0], v[1]); upk2(acc[i][1], v[2], v[3]);
        upk2(acc[i][2], v[4], v[5]); upk2(acc[i][3], v[6], v[7]);
#pragma unroll
        for (int u = 0; u < 8; ++u) {
            int n = 256 + n0 + u;
            ng[i][u] = tanhf(v[u] + __ldg(&bih[n]) + rg[i][u] * __ldg(&bhh[n]));
        }
    }
    __syncthreads();

    stage_wT(wih + 1 * 128 * 128, Ws, tid);
    __syncthreads();
#pragma unroll
    for (int i = 0; i < 4; ++i)
#pragma unroll
        for (int j = 0; j < 4; ++j) acc[i][j] = 0ull;
    gemm4x8_s132(V0, V1, V2, V3, Ws, n0, acc);
#pragma unroll
    for (int i = 0; i < 4; ++i) {
        float v[8];
        upk2(acc[i][0], v[0], v[1]); upk2(acc[i][1], v[2], v[3]);
        upk2(acc[i][2], v[4], v[5]); upk2(acc[i][3], v[6], v[7]);
        float mvals[8];
#pragma unroll
        for (int u = 0; u < 8; ++u) {
            int n = 128 + n0 + u;
            float z = sigm(v[u] + __ldg(&bih[n]) + __ldg(&bhh[n]));
            mvals[u] = (1.0f - z) * ng[i][u];
        }
        float4* dst = (float4*)&Ms[(m0 + i) * 132 + n0];
        dst[0] = make_float4(mvals[0], mvals[1], mvals[2], mvals[3]);
        dst[1] = make_float4(mvals[4], mvals[5], mvals[6], mvals[7]);
    }
    __syncthreads();

    stage_wT(ow, Ws, tid);
    __syncthreads();
#pragma unroll
    for (int i = 0; i < 4; ++i)
#pragma unroll
        for (int j = 0; j < 4; ++j) acc[i][j] = 0ull;
    gemm4x8_s132(&Ms[(m0 + 0) * 132], &Ms[(m0 + 1) * 132],
                 &Ms[(m0 + 2) * 132], &Ms[(m0 + 3) * 132], Ws, n0, acc);
#pragma unroll
    for (int i = 0; i < 4; ++i) {
        int nd = base + m0 + i;
        if (nd < NN) {
            float v[8];
            upk2(acc[i][0], v[0], v[1]); upk2(acc[i][1], v[2], v[3]);
            upk2(acc[i][2], v[4], v[5]); upk2(acc[i][3], v[6], v[7]);
#pragma unroll
            for (int u = 0; u < 8; ++u) v[u] += __ldg(&ob[n0 + u]);
            float4* dst = (float4*)&out[(size_t)nd * 128 + n0];
            dst[0] = make_float4(v[0], v[1], v[2], v[3]);
            dst[1] = make_float4(v[4], v[5], v[6], v[7]);
        }
    }
}

// ================= launch =================
extern "C" void kernel_launch(void* const* d_in, const int* in_sizes, int n_in,
                              void* d_out, int out_size) {
    const float* x     = (const float*)d_in[0];
    const float* eattr = (const float*)d_in[1];
    const float* t     = (const float*)d_in[2];
    const float* tw    = (const float*)d_in[3];
    const float* tb    = (const float*)d_in[4];
    const float* w1    = (const float*)d_in[5];
    const float* b1    = (const float*)d_in[6];
    const float* w2    = (const float*)d_in[7];
    const float* b2    = (const float*)d_in[8];
    const float* wih   = (const float*)d_in[9];
    const float* bih   = (const float*)d_in[11];
    const float* bhh   = (const float*)d_in[12];
    const float* ow    = (const float*)d_in[13];
    const float* ob    = (const float*)d_in[14];
    const int*   ei    = (const int*)d_in[15];
    float* out = (float*)d_out;

    cudaFuncSetAttribute(edge_kernel, cudaFuncAttributeMaxDynamicSharedMemorySize, EDGE_SMEM_BYTES);
    cudaFuncSetAttribute(node_kernel, cudaFuncAttributeMaxDynamicSharedMemorySize, NODE_SMEM_BYTES);

    zero_kernel<<<256, 256>>>();
    edge_kernel<<<148, 256, EDGE_SMEM_BYTES>>>(x, eattr, t, tw, tb, w1, b1, w2, b2, ei);
    node_kernel<<<(NN + NK_BM - 1) / NK_BM, 256, NODE_SMEM_BYTES>>>(wih, bih, bhh, ow, ob, out);
}

// round 5
// speedup vs baseline: 3.8263x; 1.3799x over previous
#include <cuda_runtime.h>
#include <cuda_bf16.h>
#include <math.h>
#include <stdint.h>

#define NN 50000
#define NE 800000
#define NODE_F 128
#define EDGE_F 32
#define TIME_D 16
#define K1 176
#define DN 128

typedef unsigned long long ull;

// ---------------- scratch ----------------
__device__ float g_agg[(size_t)NN * 128];
__device__ float g_cnt[NN];
__device__ uint32_t g_xhi[(size_t)NN * 64];        // x hi, bf16x2 packed
__device__ uint32_t g_xlo[(size_t)NN * 64];        // x lo
__device__ uint32_t g_thi[(size_t)NE * 24];        // tail (attr|time) hi, 48 bf16
__device__ uint32_t g_tlo[(size_t)NE * 24];        // tail lo

// ---------------- helpers ----------------
__device__ __forceinline__ uint32_t smem_u32(const void* p) {
    uint32_t a;
    asm("{ .reg .u64 t; cvta.to.shared.u64 t, %1; cvt.u32.u64 %0, t; }" : "=r"(a) : "l"(p));
    return a;
}
__device__ __forceinline__ ull pk2(float lo, float hi) {
    ull r; asm("mov.b64 %0, {%1,%2};" : "=l"(r) : "f"(lo), "f"(hi)); return r;
}
__device__ __forceinline__ ull dup2(float v) {
    ull r; asm("mov.b64 %0, {%1,%1};" : "=l"(r) : "f"(v)); return r;
}
__device__ __forceinline__ void upk2(ull p, float& lo, float& hi) {
    asm("mov.b64 {%0,%1}, %2;" : "=f"(lo), "=f"(hi) : "l"(p));
}
__device__ __forceinline__ ull ffma2(ull a, ull b, ull c) {
    ull d; asm("fma.rn.f32x2 %0, %1, %2, %3;" : "=l"(d) : "l"(a), "l"(b), "l"(c)); return d;
}
__device__ __forceinline__ float sigm(float x) { return 1.0f / (1.0f + expf(-x)); }

__device__ __forceinline__ void split1(float v, __nv_bfloat16& h, __nv_bfloat16& l) {
    h = __float2bfloat16(v);
    l = __float2bfloat16(v - __bfloat162float(h));
}
// packed pair split: (a,b) -> hi u32, lo u32
__device__ __forceinline__ void split2(float a, float b, uint32_t& h, uint32_t& l) {
    __nv_bfloat162 hh = __floats2bfloat162_rn(a, b);
    float ra = a - __bfloat162float(hh.x);
    float rb = b - __bfloat162float(hh.y);
    __nv_bfloat162 ll = __floats2bfloat162_rn(ra, rb);
    h = *reinterpret_cast<uint32_t*>(&hh);
    l = *reinterpret_cast<uint32_t*>(&ll);
}

__device__ __forceinline__ void ldsm_x4(uint32_t& r0, uint32_t& r1, uint32_t& r2, uint32_t& r3,
                                        uint32_t addr) {
    asm volatile("ldmatrix.sync.aligned.m8n8.x4.shared.b16 {%0,%1,%2,%3}, [%4];"
                 : "=r"(r0), "=r"(r1), "=r"(r2), "=r"(r3) : "r"(addr));
}
__device__ __forceinline__ void mma_bf16(float* d, const uint32_t* a, const uint32_t* b) {
    asm volatile("mma.sync.aligned.m16n8k16.row.col.f32.bf16.bf16.f32 "
                 "{%0,%1,%2,%3}, {%4,%5,%6,%7}, {%8,%9}, {%0,%1,%2,%3};"
                 : "+f"(d[0]), "+f"(d[1]), "+f"(d[2]), "+f"(d[3])
                 : "r"(a[0]), "r"(a[1]), "r"(a[2]), "r"(a[3]), "r"(b[0]), "r"(b[1]));
}
__device__ __forceinline__ void cp16(uint32_t s, const void* g) {
    asm volatile("cp.async.ca.shared.global [%0], [%1], 16;" :: "r"(s), "l"(g));
}
#define CP_COMMIT() asm volatile("cp.async.commit_group;" ::: "memory")
#define CP_WAIT0()  asm volatile("cp.async.wait_group 0;" ::: "memory")
#define GBAR(id)    asm volatile("bar.sync %0, 128;" :: "r"(id) : "memory")

// ---------------- zero scratch ----------------
__global__ void zero_kernel() {
    int i = blockIdx.x * blockDim.x + threadIdx.x;
    int stride = gridDim.x * blockDim.x;
    float4 z = make_float4(0.f, 0.f, 0.f, 0.f);
    float4* a4 = reinterpret_cast<float4*>(g_agg);
    for (int j = i; j < NN * 128 / 4; j += stride) a4[j] = z;
    for (int j = i; j < NN; j += stride) g_cnt[j] = 0.f;
}

// ---------------- precompute: x hi/lo split ----------------
__global__ void split_x_kernel(const float* __restrict__ x) {
    int i = blockIdx.x * blockDim.x + threadIdx.x;
    if (i < NN * 64) {
        float2 f = __ldg(&((const float2*)x)[i]);
        uint32_t h, l;
        split2(f.x, f.y, h, l);
        g_xhi[i] = h;
        g_xlo[i] = l;
    }
}

// ---------------- precompute: per-edge tail (attr|time) + cnt ----------------
__global__ void edge_pre_kernel(const float* __restrict__ eattr, const float* __restrict__ tt,
                                const float* __restrict__ tw, const float* __restrict__ tb,
                                const int* __restrict__ ei) {
    int e = blockIdx.x * blockDim.x + threadIdx.x;
    if (e >= NE) return;
    uint32_t th[24], tl[24];
    const float4* er = (const float4*)(eattr + (size_t)e * 32);
#pragma unroll
    for (int i = 0; i < 8; ++i) {
        float4 f = __ldg(&er[i]);
        split2(f.x, f.y, th[2 * i],     tl[2 * i]);
        split2(f.z, f.w, th[2 * i + 1], tl[2 * i + 1]);
    }
    float tv = __ldg(&tt[e]);
#pragma unroll
    for (int d = 0; d < 8; ++d) {
        float a = cosf(tv * __ldg(&tw[2 * d])     + __ldg(&tb[2 * d]));
        float b = cosf(tv * __ldg(&tw[2 * d + 1]) + __ldg(&tb[2 * d + 1]));
        split2(a, b, th[16 + d], tl[16 + d]);
    }
    uint4* dh = (uint4*)(g_thi + (size_t)e * 24);
    uint4* dl = (uint4*)(g_tlo + (size_t)e * 24);
#pragma unroll
    for (int q = 0; q < 6; ++q) {
        dh[q] = make_uint4(th[4 * q], th[4 * q + 1], th[4 * q + 2], th[4 * q + 3]);
        dl[q] = make_uint4(tl[4 * q], tl[4 * q + 1], tl[4 * q + 2], tl[4 * q + 3]);
    }
    atomicAdd(&g_cnt[__ldg(&ei[NE + e])], 1.0f);
}

// ================= EDGE KERNEL (ping-pong groups, mma.sync bf16x3) =================
#define EK_M   32          // edges per group-tile
#define NT32   (NE / EK_M) // 25000
#define LDA    184
#define LDH    136
#define A_BYTES 11776      // 32*184*2
#define GRP_BYTES 23552    // A_hi + A_lo

// smem byte offsets
#define SM_W1_HI  0
#define SM_W1_LO  47104
#define SM_W2_HI  94208
#define SM_W2_LO  129024
#define SM_A      163840   // + half*GRP_BYTES; A_lo/H_lo at +A_BYTES
#define SM_B1     210944
#define SM_B2     211456
#define SM_TGT    211968   // 2*32 ints
#define EDGE_SMEM_BYTES 212224

__global__ __launch_bounds__(256, 1)
void edge_kernel(const float* __restrict__ w1, const float* __restrict__ b1,
                 const float* __restrict__ w2, const float* __restrict__ b2,
                 const int* __restrict__ ei)
{
    extern __shared__ char smc[];
    const uint32_t smb = smem_u32(smc);
    const int tid = threadIdx.x;
    const int wid = tid >> 5, lane = tid & 31;
    const int half = wid >> 2;                 // group 0/1
    const int gw = wid & 3;                    // warp within group (one per SMSP)
    const int wm = gw & 1, wn = gw >> 1;
    const int m0 = wm * 16;                    // group-local row base
    const int nbase = wn * 64;
    const int gt = tid & 127;                  // thread within group

    float* b1s = (float*)(smc + SM_B1);
    float* b2s = (float*)(smc + SM_B2);
    int*   tgts = (int*)(smc + SM_TGT);

    // ---- stage weights (all 256 threads) ----
    for (int idx = tid; idx < K1 * DN; idx += 256) {
        int k = idx >> 7, n = idx & 127;
        __nv_bfloat16 h, l;
        split1(w1[idx], h, l);
        *(__nv_bfloat16*)(smc + SM_W1_HI + 2 * (n * LDA + k)) = h;
        *(__nv_bfloat16*)(smc + SM_W1_LO + 2 * (n * LDA + k)) = l;
    }
    for (int idx = tid; idx < DN * DN; idx += 256) {
        int k = idx >> 7, n = idx & 127;
        __nv_bfloat16 h, l;
        split1(w2[idx], h, l);
        *(__nv_bfloat16*)(smc + SM_W2_HI + 2 * (n * LDH + k)) = h;
        *(__nv_bfloat16*)(smc + SM_W2_LO + 2 * (n * LDH + k)) = l;
    }
    for (int i = tid; i < 128; i += 256) { b1s[i] = b1[i]; b2s[i] = b2[i]; }
    __syncthreads();    // last CTA-wide sync; groups now independent

    const uint32_t grpBase = smb + SM_A + half * GRP_BYTES;
    const int barId = 1 + half;

    // fragment lane addressing (group-relative, bytes)
    const uint32_t aRowOff = (uint32_t)((m0 + (lane & 15)) * LDA + ((lane >> 4) << 3)) * 2;
    const uint32_t hRowOff = (uint32_t)((m0 + (lane & 15)) * LDH + ((lane >> 4) << 3)) * 2;
    const uint32_t bRow = (uint32_t)((lane & 7) + ((lane >> 4) << 3));
    const uint32_t bColPiece = (uint32_t)(((lane >> 3) & 1) << 3);
    const uint32_t b1LaneOff = (uint32_t)(bRow * LDA + bColPiece) * 2;
    const uint32_t b2LaneOff = (uint32_t)(bRow * LDH + bColPiece) * 2;
    const int crow = lane >> 2;
    const int ccol = (lane & 3) * 2;

    for (int tile = blockIdx.x * 2 + half; tile < NT32; tile += 2 * gridDim.x) {
        const int ebase = tile * EK_M;

        // ---------- build A tile via cp.async gather (precomputed splits) ----------
        {
            const int e = gt >> 2, sub = gt & 3;
            const int ge = ebase + e;
            const int src = __ldg(&ei[ge]);
            const char* xh = (const char*)g_xhi + (size_t)src * 256;
            const char* xl = (const char*)g_xlo + (size_t)src * 256;
            const char* th = (const char*)g_thi + (size_t)ge * 96;
            const char* tl = (const char*)g_tlo + (size_t)ge * 96;
            const uint32_t arow = grpBase + (uint32_t)e * (LDA * 2);
            for (int c = sub; c < 16; c += 4) {
                cp16(arow + c * 16,            xh + c * 16);
                cp16(arow + A_BYTES + c * 16,  xl + c * 16);
            }
            for (int c = sub; c < 6; c += 4) {
                cp16(arow + 256 + c * 16,           th + c * 16);
                cp16(arow + A_BYTES + 256 + c * 16, tl + c * 16);
            }
            if (sub == 0) tgts[half * 32 + e] = __ldg(&ei[NE + ge]);
            CP_COMMIT();
            CP_WAIT0();
        }
        GBAR(barId);

        // ---------- GEMM1: D1 = A(176) @ W1, bf16x3 ----------
        float acc[8][4];
#pragma unroll
        for (int j = 0; j < 8; ++j)
#pragma unroll
            for (int q = 0; q < 4; ++q) acc[j][q] = 0.f;

        for (int ks = 0; ks < 11; ++ks) {
            const uint32_t kOff = (uint32_t)(ks * 16) * 2;
            uint32_t ah[4], al[4];
            ldsm_x4(ah[0], ah[1], ah[2], ah[3], grpBase + aRowOff + kOff);
            ldsm_x4(al[0], al[1], al[2], al[3], grpBase + A_BYTES + aRowOff + kOff);
#pragma unroll
            for (int jj = 0; jj < 4; ++jj) {
                const uint32_t nOff = (uint32_t)((nbase + jj * 16) * LDA) * 2;
                uint32_t bh[4], bl[4];
                ldsm_x4(bh[0], bh[1], bh[2], bh[3], smb + SM_W1_HI + b1LaneOff + nOff + kOff);
                ldsm_x4(bl[0], bl[1], bl[2], bl[3], smb + SM_W1_LO + b1LaneOff + nOff + kOff);
                mma_bf16(acc[2 * jj],     ah, bh);
                mma_bf16(acc[2 * jj + 1], ah, bh + 2);
                mma_bf16(acc[2 * jj],     ah, bl);
                mma_bf16(acc[2 * jj + 1], ah, bl + 2);
                mma_bf16(acc[2 * jj],     al, bh);
                mma_bf16(acc[2 * jj + 1], al, bh + 2);
            }
        }
        GBAR(barId);   // group done reading A before H overlay write

        // ---------- epilogue 1: relu(D1 + b1) -> H (hi/lo, overlays A) ----------
#pragma unroll
        for (int j = 0; j < 8; ++j) {
            int n = nbase + j * 8 + ccol;
            float v0 = fmaxf(acc[j][0] + b1s[n],     0.f);
            float v1 = fmaxf(acc[j][1] + b1s[n + 1], 0.f);
            float v2 = fmaxf(acc[j][2] + b1s[n],     0.f);
            float v3 = fmaxf(acc[j][3] + b1s[n + 1], 0.f);
            __nv_bfloat162 h01, l01, h23, l23;
            split1(v0, h01.x, l01.x); split1(v1, h01.y, l01.y);
            split1(v2, h23.x, l23.x); split1(v3, h23.y, l23.y);
            int r0 = m0 + crow, r1 = m0 + crow + 8;
            *(__nv_bfloat162*)(smc + (grpBase - smb) + 2 * (r0 * LDH + n)) = h01;
            *(__nv_bfloat162*)(smc + (grpBase - smb) + A_BYTES + 2 * (r0 * LDH + n)) = l01;
            *(__nv_bfloat162*)(smc + (grpBase - smb) + 2 * (r1 * LDH + n)) = h23;
            *(__nv_bfloat162*)(smc + (grpBase - smb) + A_BYTES + 2 * (r1 * LDH + n)) = l23;
        }
        GBAR(barId);

        // ---------- GEMM2: D2 = H(128) @ W2, bf16x3 ----------
#pragma unroll
        for (int j = 0; j < 8; ++j)
#pragma unroll
            for (int q = 0; q < 4; ++q) acc[j][q] = 0.f;

        for (int ks = 0; ks < 8; ++ks) {
            const uint32_t kOff = (uint32_t)(ks * 16) * 2;
            uint32_t ah[4], al[4];
            ldsm_x4(ah[0], ah[1], ah[2], ah[3], grpBase + hRowOff + kOff);
            ldsm_x4(al[0], al[1], al[2], al[3], grpBase + A_BYTES + hRowOff + kOff);
#pragma unroll
            for (int jj = 0; jj < 4; ++jj) {
                const uint32_t nOff = (uint32_t)((nbase + jj * 16) * LDH) * 2;
                uint32_t bh[4], bl[4];
                ldsm_x4(bh[0], bh[1], bh[2], bh[3], smb + SM_W2_HI + b2LaneOff + nOff + kOff);
                ldsm_x4(bl[0], bl[1], bl[2], bl[3], smb + SM_W2_LO + b2LaneOff + nOff + kOff);
                mma_bf16(acc[2 * jj],     ah, bh);
                mma_bf16(acc[2 * jj + 1], ah, bh + 2);
                mma_bf16(acc[2 * jj],     ah, bl);
                mma_bf16(acc[2 * jj + 1], ah, bl + 2);
                mma_bf16(acc[2 * jj],     al, bh);
                mma_bf16(acc[2 * jj + 1], al, bh + 2);
            }
        }
        GBAR(barId);   // group done reading H before next tile's A overwrite

        // ---------- epilogue 2: scatter D2 + b2 into g_agg ----------
        {
            int tg0 = tgts[half * 32 + m0 + crow];
            int tg1 = tgts[half * 32 + m0 + crow + 8];
            size_t ga0 = __cvta_generic_to_global(&g_agg[(size_t)tg0 * 128]);
            size_t ga1 = __cvta_generic_to_global(&g_agg[(size_t)tg1 * 128]);
#pragma unroll
            for (int j = 0; j < 8; ++j) {
                int n = nbase + j * 8 + ccol;
                float v0 = acc[j][0] + b2s[n];
                float v1 = acc[j][1] + b2s[n + 1];
                float v2 = acc[j][2] + b2s[n];
                float v3 = acc[j][3] + b2s[n + 1];
                asm volatile("red.global.add.v2.f32 [%0], {%1,%2};"
                             :: "l"(ga0 + (size_t)n * 4), "f"(v0), "f"(v1) : "memory");
                asm volatile("red.global.add.v2.f32 [%0], {%1,%2};"
                             :: "l"(ga1 + (size_t)n * 4), "f"(v2), "f"(v3) : "memory");
            }
        }
        GBAR(barId);   // scatter reads tgts done before next tile overwrites
    }
}

// ================= NODE KERNEL (unchanged) =================
#define NK_BM 64
#define NODE_SMEM_BYTES ((8448 + 16896 + 8448) * 4)

__device__ __forceinline__ void stage_wT(const float* __restrict__ src, float* Ws, int tid) {
    for (int idx = tid; idx < 128 * 128; idx += 256) {
        int j = idx >> 7, k = idx & 127;
        Ws[k * 132 + j] = __ldg(&src[j * 128 + k]);
    }
}

__device__ __forceinline__ void gemm4x8_s132(const float* __restrict__ A0,
                                             const float* __restrict__ A1,
                                             const float* __restrict__ A2,
                                             const float* __restrict__ A3,
                                             const float* __restrict__ Ws,
                                             int n0, ull acc[4][4]) {
#pragma unroll 4
    for (int k = 0; k < 128; ++k) {
        ull a0 = dup2(A0[k]), a1 = dup2(A1[k]), a2 = dup2(A2[k]), a3 = dup2(A3[k]);
        float4 bA = *(const float4*)&Ws[k * 132 + n0];
        float4 bB = *(const float4*)&Ws[k * 132 + n0 + 4];
        ull db0 = pk2(bA.x, bA.y), db1 = pk2(bA.z, bA.w);
        ull db2 = pk2(bB.x, bB.y), db3 = pk2(bB.z, bB.w);
        acc[0][0] = ffma2(a0, db0, acc[0][0]); acc[0][1] = ffma2(a0, db1, acc[0][1]);
        acc[0][2] = ffma2(a0, db2, acc[0][2]); acc[0][3] = ffma2(a0, db3, acc[0][3]);
        acc[1][0] = ffma2(a1, db0, acc[1][0]); acc[1][1] = ffma2(a1, db1, acc[1][1]);
        acc[1][2] = ffma2(a1, db2, acc[1][2]); acc[1][3] = ffma2(a1, db3, acc[1][3]);
        acc[2][0] = ffma2(a2, db0, acc[2][0]); acc[2][1] = ffma2(a2, db1, acc[2][1]);
        acc[2][2] = ffma2(a2, db2, acc[2][2]); acc[2][3] = ffma2(a2, db3, acc[2][3]);
        acc[3][0] = ffma2(a3, db0, acc[3][0]); acc[3][1] = ffma2(a3, db1, acc[3][1]);
        acc[3][2] = ffma2(a3, db2, acc[3][2]); acc[3][3] = ffma2(a3, db3, acc[3][3]);
    }
}

__global__ __launch_bounds__(256, 1)
void node_kernel(const float* __restrict__ wih, const float* __restrict__ bih,
                 const float* __restrict__ bhh, const float* __restrict__ ow,
                 const float* __restrict__ ob, float* __restrict__ out)
{
    extern __shared__ float sm[];
    float* Vs = sm;
    float* Ws = Vs + 8448;
    float* Ms = Ws + 16896;

    const int tid = threadIdx.x;
    const int base = blockIdx.x * NK_BM;

    for (int idx = tid; idx < NK_BM * 128; idx += 256) {
        int m = idx >> 7, f = idx & 127;
        int nd = base + m;
        float v = 0.f;
        if (nd < NN) v = g_agg[(size_t)nd * 128 + f] / fmaxf(g_cnt[nd], 1.0f);
        Vs[m * 132 + f] = v;
    }

    const int tn = tid & 15, tm0 = tid >> 4;
    const int m0 = tm0 * 4, n0 = tn * 8;

    const float* V0 = &Vs[(m0 + 0) * 132];
    const float* V1 = &Vs[(m0 + 1) * 132];
    const float* V2 = &Vs[(m0 + 2) * 132];
    const float* V3 = &Vs[(m0 + 3) * 132];

    ull acc[4][4];
    float rg[4][8];
    float ng[4][8];

    stage_wT(wih, Ws, tid);
    __syncthreads();
#pragma unroll
    for (int i = 0; i < 4; ++i)
#pragma unroll
        for (int j = 0; j < 4; ++j) acc[i][j] = 0ull;
    gemm4x8_s132(V0, V1, V2, V3, Ws, n0, acc);
#pragma unroll
    for (int i = 0; i < 4; ++i) {
        float v[8];
        upk2(acc[i][0], v[0], v[1]); upk2(acc[i][1], v[2], v[3]);
        upk2(acc[i][2], v[4], v[5]); upk2(acc[i][3], v[6], v[7]);
#pragma unroll
        for (int u = 0; u < 8; ++u) {
            int n = n0 + u;
            rg[i][u] = sigm(v[u] + __ldg(&bih[n]) + __ldg(&bhh[n]));
        }
    }
    __syncthreads();

    stage_wT(wih + 2 * 128 * 128, Ws, tid);
    __syncthreads();
#pragma unroll
    for (int i = 0; i < 4; ++i)
#pragma unroll
        for (int j = 0; j < 4; ++j) acc[i][j] = 0ull;
    gemm4x8_s132(V0, V1, V2, V3, Ws, n0, acc);
#pragma unroll
    for (int i = 0; i < 4; ++i) {
        float v[8];
        upk2(acc[i][0], v[0], v[1]); upk2(acc[i][1], v[2], v[3]);
        upk2(acc[i][2], v[4], v[5]); upk2(acc[i][3], v[6], v[7]);
#pragma unroll
        for (int u = 0; u < 8; ++u) {
            int n = 256 + n0 + u;
            ng[i][u] = tanhf(v[u] + __ldg(&bih[n]) + rg[i][u] * __ldg(&bhh[n]));
        }
    }
    __syncthreads();

    stage_wT(wih + 1 * 128 * 128, Ws, tid);
    __syncthreads();
#pragma unroll
    for (int i = 0; i < 4; ++i)
#pragma unroll
        for (int j = 0; j < 4; ++j) acc[i][j] = 0ull;
    gemm4x8_s132(V0, V1, V2, V3, Ws, n0, acc);
#pragma unroll
    for (int i = 0; i < 4; ++i) {
        float v[8];
        upk2(acc[i][0], v[0], v[1]); upk2(acc[i][1], v[2], v[3]);
        upk2(acc[i][2], v[4], v[5]); upk2(acc[i][3], v[6], v[7]);
        float mvals[8];
#pragma unroll
        for (int u = 0; u < 8; ++u) {
            int n = 128 + n0 + u;
            float z = sigm(v[u] + __ldg(&bih[n]) + __ldg(&bhh[n]));
            mvals[u] = (1.0f - z) * ng[i][u];
        }
        float4* dst = (float4*)&Ms[(m0 + i) * 132 + n0];
        dst[0] = make_float4(mvals[0], mvals[1], mvals[2], mvals[3]);
        dst[1] = make_float4(mvals[4], mvals[5], mvals[6], mvals[7]);
    }
    __syncthreads();

    stage_wT(ow, Ws, tid);
    __syncthreads();
#pragma unroll
    for (int i = 0; i < 4; ++i)
#pragma unroll
        for (int j = 0; j < 4; ++j) acc[i][j] = 0ull;
    gemm4x8_s132(&Ms[(m0 + 0) * 132], &Ms[(m0 + 1) * 132],
                 &Ms[(m0 + 2) * 132], &Ms[(m0 + 3) * 132], Ws, n0, acc);
#pragma unroll
    for (int i = 0; i < 4; ++i) {
        int nd = base + m0 + i;
        if (nd < NN) {
            float v[8];
            upk2(acc[i][0], v[0], v[1]); upk2(acc[i][1], v[2], v[3]);
            upk2(acc[i][2], v[4], v[5]); upk2(acc[i][3], v[6], v[7]);
#pragma unroll
            for (int u = 0; u < 8; ++u) v[u] += __ldg(&ob[n0 + u]);
            float4* dst = (float4*)&out[(size_t)nd * 128 + n0];
            dst[0] = make_float4(v[0], v[1], v[2], v[3]);
            dst[1] = make_float4(v[4], v[5], v[6], v[7]);
        }
    }
}

// ================= launch =================
extern "C" void kernel_launch(void* const* d_in, const int* in_sizes, int n_in,
                              void* d_out, int out_size) {
    const float* x     = (const float*)d_in[0];
    const float* eattr = (const float*)d_in[1];
    const float* t     = (const float*)d_in[2];
    const float* tw    = (const float*)d_in[3];
    const float* tb    = (const float*)d_in[4];
    const float* w1    = (const float*)d_in[5];
    const float* b1    = (const float*)d_in[6];
    const float* w2    = (const float*)d_in[7];
    const float* b2    = (const float*)d_in[8];
    const float* wih   = (const float*)d_in[9];
    const float* bih   = (const float*)d_in[11];
    const float* bhh   = (const float*)d_in[12];
    const float* ow    = (const float*)d_in[13];
    const float* ob    = (const float*)d_in[14];
    const int*   ei    = (const int*)d_in[15];
    float* out = (float*)d_out;

    cudaFuncSetAttribute(edge_kernel, cudaFuncAttributeMaxDynamicSharedMemorySize, EDGE_SMEM_BYTES);
    cudaFuncSetAttribute(node_kernel, cudaFuncAttributeMaxDynamicSharedMemorySize, NODE_SMEM_BYTES);

    zero_kernel<<<256, 256>>>();
    split_x_kernel<<<(NN * 64 + 255) / 256, 256>>>(x);
    edge_pre_kernel<<<(NE + 255) / 256, 256>>>(eattr, t, tw, tb, ei);
    edge_kernel<<<148, 256, EDGE_SMEM_BYTES>>>(w1, b1, w2, b2, ei);
    node_kernel<<<(NN + NK_BM - 1) / NK_BM, 256, NODE_SMEM_BYTES>>>(wih, bih, bhh, ow, ob, out);
}

// round 6
// speedup vs baseline: 6.5409x; 1.7094x over previous
#include <cuda_runtime.h>
#include <cuda_bf16.h>
#include <cuda_fp16.h>
#include <math.h>
#include <stdint.h>

#define NN 50000
#define NE 800000
#define NODE_F 128
#define EDGE_F 32
#define TIME_D 16
#define K1 176
#define DN 128

typedef unsigned long long ull;

// ---------------- scratch ----------------
__device__ float g_agg[(size_t)NN * 128];
__device__ float g_cnt[NN];
__device__ uint32_t g_xf16[(size_t)NN * 64];       // x as f16x2
__device__ uint32_t g_tf16[(size_t)NE * 24];       // tail (attr|time) as f16x2, 48 vals

// ---------------- helpers ----------------
__device__ __forceinline__ uint32_t smem_u32(const void* p) {
    uint32_t a;
    asm("{ .reg .u64 t; cvta.to.shared.u64 t, %1; cvt.u32.u64 %0, t; }" : "=r"(a) : "l"(p));
    return a;
}
__device__ __forceinline__ float sigm(float x) { return 1.0f / (1.0f + expf(-x)); }

__device__ __forceinline__ uint32_t h2u(float a, float b) {
    __half2 h = __floats2half2_rn(a, b);
    return *reinterpret_cast<uint32_t*>(&h);
}
__device__ __forceinline__ void fsplit(float v, __half& h, __half& l) {
    h = __float2half_rn(v);
    l = __float2half_rn(v - __half2float(h));
}

__device__ __forceinline__ void ldsm_x4(uint32_t& r0, uint32_t& r1, uint32_t& r2, uint32_t& r3,
                                        uint32_t addr) {
    asm volatile("ldmatrix.sync.aligned.m8n8.x4.shared.b16 {%0,%1,%2,%3}, [%4];"
                 : "=r"(r0), "=r"(r1), "=r"(r2), "=r"(r3) : "r"(addr));
}
__device__ __forceinline__ void mma_f16(float* d, const uint32_t* a, const uint32_t* b) {
    asm volatile("mma.sync.aligned.m16n8k16.row.col.f32.f16.f16.f32 "
                 "{%0,%1,%2,%3}, {%4,%5,%6,%7}, {%8,%9}, {%0,%1,%2,%3};"
                 : "+f"(d[0]), "+f"(d[1]), "+f"(d[2]), "+f"(d[3])
                 : "r"(a[0]), "r"(a[1]), "r"(a[2]), "r"(a[3]), "r"(b[0]), "r"(b[1]));
}
__device__ __forceinline__ void cp16(uint32_t s, const void* g) {
    asm volatile("cp.async.ca.shared.global [%0], [%1], 16;" :: "r"(s), "l"(g));
}
#define CP_COMMIT() asm volatile("cp.async.commit_group;" ::: "memory")
#define CP_WAIT1()  asm volatile("cp.async.wait_group 1;" ::: "memory")
#define GBAR(id)    asm volatile("bar.sync %0, 128;" :: "r"(id) : "memory")

// ---------------- zero scratch ----------------
__global__ void zero_kernel() {
    int i = blockIdx.x * blockDim.x + threadIdx.x;
    int stride = gridDim.x * blockDim.x;
    float4 z = make_float4(0.f, 0.f, 0.f, 0.f);
    float4* a4 = reinterpret_cast<float4*>(g_agg);
    for (int j = i; j < NN * 128 / 4; j += stride) a4[j] = z;
    for (int j = i; j < NN; j += stride) g_cnt[j] = 0.f;
}

// ---------------- precompute: x -> f16 ----------------
__global__ void split_x_kernel(const float* __restrict__ x) {
    int i = blockIdx.x * blockDim.x + threadIdx.x;
    if (i < NN * 64) {
        float2 f = __ldg(&((const float2*)x)[i]);
        g_xf16[i] = h2u(f.x, f.y);
    }
}

// ---------------- precompute: per-edge tail + cnt ----------------
__global__ void edge_pre_kernel(const float* __restrict__ eattr, const float* __restrict__ tt,
                                const float* __restrict__ tw, const float* __restrict__ tb,
                                const int* __restrict__ ei) {
    int e = blockIdx.x * blockDim.x + threadIdx.x;
    if (e >= NE) return;
    uint32_t th[24];
    const float4* er = (const float4*)(eattr + (size_t)e * 32);
#pragma unroll
    for (int i = 0; i < 8; ++i) {
        float4 f = __ldg(&er[i]);
        th[2 * i]     = h2u(f.x, f.y);
        th[2 * i + 1] = h2u(f.z, f.w);
    }
    float tv = __ldg(&tt[e]);
#pragma unroll
    for (int d = 0; d < 8; ++d) {
        float a = cosf(tv * __ldg(&tw[2 * d])     + __ldg(&tb[2 * d]));
        float b = cosf(tv * __ldg(&tw[2 * d + 1]) + __ldg(&tb[2 * d + 1]));
        th[16 + d] = h2u(a, b);
    }
    uint4* dh = (uint4*)(g_tf16 + (size_t)e * 24);
#pragma unroll
    for (int q = 0; q < 6; ++q)
        dh[q] = make_uint4(th[4 * q], th[4 * q + 1], th[4 * q + 2], th[4 * q + 3]);
    atomicAdd(&g_cnt[__ldg(&ei[NE + e])], 1.0f);
}

// ================= EDGE KERNEL =================
#define EK_M   32
#define NT32   (NE / EK_M)
#define LDA    184
#define LDH    136
#define A_BYTES 11776      // 32*184*2

// smem byte offsets
#define SM_W1_HI  0
#define SM_W1_LO  47104
#define SM_W2_HI  94208
#define SM_W2_LO  129024
#define SM_A      163840   // 4 buffers of A_BYTES: (group*2+buf)
#define SM_H      210944   // 2 groups of 8704
#define SM_B1     228352
#define SM_B2     228864
#define SM_TGT    229376   // (group*2+buf)*32 ints
#define EDGE_SMEM_BYTES 229888

__device__ __forceinline__ void prefetch_tile(int tile, uint32_t aBase, int* tgtS,
                                              const int* __restrict__ ei, int gt) {
    const int e = gt >> 2, sub = gt & 3;
    const int ge = tile * EK_M + e;
    const int src = __ldg(&ei[ge]);
    const char* xf = (const char*)g_xf16 + (size_t)src * 256;
    const char* tf = (const char*)g_tf16 + (size_t)ge * 96;
    const uint32_t arow = aBase + (uint32_t)e * (LDA * 2);
#pragma unroll
    for (int c = sub; c < 16; c += 4) cp16(arow + c * 16, xf + c * 16);
#pragma unroll
    for (int c = sub; c < 6; c += 4)  cp16(arow + 256 + c * 16, tf + c * 16);
    if (sub == 0) tgtS[e] = __ldg(&ei[NE + ge]);
}

__global__ __launch_bounds__(256, 1)
void edge_kernel(const float* __restrict__ w1, const float* __restrict__ b1,
                 const float* __restrict__ w2, const float* __restrict__ b2,
                 const int* __restrict__ ei)
{
    extern __shared__ char smc[];
    const uint32_t smb = smem_u32(smc);
    const int tid = threadIdx.x;
    const int wid = tid >> 5, lane = tid & 31;
    const int half = wid >> 2;
    const int gw = wid & 3;
    const int wm = gw & 1, wn = gw >> 1;
    const int m0 = wm * 16;
    const int nbase = wn * 64;
    const int gt = tid & 127;

    float* b1s = (float*)(smc + SM_B1);
    float* b2s = (float*)(smc + SM_B2);

    // ---- stage weights (f16 hi/lo, [n][k]) ----
    for (int idx = tid; idx < K1 * DN; idx += 256) {
        int k = idx >> 7, n = idx & 127;
        __half h, l;
        fsplit(w1[idx], h, l);
        *(__half*)(smc + SM_W1_HI + 2 * (n * LDA + k)) = h;
        *(__half*)(smc + SM_W1_LO + 2 * (n * LDA + k)) = l;
    }
    for (int idx = tid; idx < DN * DN; idx += 256) {
        int k = idx >> 7, n = idx & 127;
        __half h, l;
        fsplit(w2[idx], h, l);
        *(__half*)(smc + SM_W2_HI + 2 * (n * LDH + k)) = h;
        *(__half*)(smc + SM_W2_LO + 2 * (n * LDH + k)) = l;
    }
    for (int i = tid; i < 128; i += 256) { b1s[i] = b1[i]; b2s[i] = b2[i]; }
    __syncthreads();

    const int barId = 1 + half;
    const uint32_t hBase = smb + SM_H + half * 8704;

    const uint32_t aRowOff = (uint32_t)((m0 + (lane & 15)) * LDA + ((lane >> 4) << 3)) * 2;
    const uint32_t hRowOff = (uint32_t)((m0 + (lane & 15)) * LDH + ((lane >> 4) << 3)) * 2;
    const uint32_t bRow = (uint32_t)((lane & 7) + ((lane >> 4) << 3));
    const uint32_t bColPiece = (uint32_t)(((lane >> 3) & 1) << 3);
    const uint32_t b1LaneOff = (uint32_t)(bRow * LDA + bColPiece) * 2;
    const uint32_t b2LaneOff = (uint32_t)(bRow * LDH + bColPiece) * 2;
    const int crow = lane >> 2;
    const int ccol = (lane & 3) * 2;

    int buf = 0;
    int tile = blockIdx.x * 2 + half;
    const int step = gridDim.x * 2;

    if (tile < NT32)
        prefetch_tile(tile, smb + SM_A + (uint32_t)(half * 2 + buf) * A_BYTES,
                      (int*)(smc + SM_TGT) + (half * 2 + buf) * 32, ei, gt);
    CP_COMMIT();

    for (; tile < NT32; tile += step) {
        const int nxt = tile + step;
        if (nxt < NT32)
            prefetch_tile(nxt, smb + SM_A + (uint32_t)(half * 2 + (buf ^ 1)) * A_BYTES,
                          (int*)(smc + SM_TGT) + (half * 2 + (buf ^ 1)) * 32, ei, gt);
        CP_COMMIT();
        CP_WAIT1();
        GBAR(barId);

        const uint32_t aBase = smb + SM_A + (uint32_t)(half * 2 + buf) * A_BYTES;
        int* tgts = (int*)(smc + SM_TGT) + (half * 2 + buf) * 32;

        // ---------- GEMM1: D1 = A(176) @ W1 (A f16, W hi/lo) ----------
        float acc[8][4];
#pragma unroll
        for (int j = 0; j < 8; ++j)
#pragma unroll
            for (int q = 0; q < 4; ++q) acc[j][q] = 0.f;

#pragma unroll
        for (int ks = 0; ks < 11; ++ks) {
            const uint32_t kOff = (uint32_t)(ks * 16) * 2;
            uint32_t a[4];
            ldsm_x4(a[0], a[1], a[2], a[3], aBase + aRowOff + kOff);
#pragma unroll
            for (int jj = 0; jj < 4; ++jj) {
                const uint32_t nOff = (uint32_t)((nbase + jj * 16) * LDA) * 2;
                uint32_t bh[4], bl[4];
                ldsm_x4(bh[0], bh[1], bh[2], bh[3], smb + SM_W1_HI + b1LaneOff + nOff + kOff);
                ldsm_x4(bl[0], bl[1], bl[2], bl[3], smb + SM_W1_LO + b1LaneOff + nOff + kOff);
                mma_f16(acc[2 * jj],     a, bh);
                mma_f16(acc[2 * jj + 1], a, bh + 2);
                mma_f16(acc[2 * jj],     a, bl);
                mma_f16(acc[2 * jj + 1], a, bl + 2);
            }
        }

        // ---------- epilogue 1: relu(D1 + b1) -> H (f16) ----------
        {
            int r0 = m0 + crow, r1 = m0 + crow + 8;
#pragma unroll
            for (int j = 0; j < 8; ++j) {
                int n = nbase + j * 8 + ccol;
                float v0 = fmaxf(acc[j][0] + b1s[n],     0.f);
                float v1 = fmaxf(acc[j][1] + b1s[n + 1], 0.f);
                float v2 = fmaxf(acc[j][2] + b1s[n],     0.f);
                float v3 = fmaxf(acc[j][3] + b1s[n + 1], 0.f);
                *(__half2*)(smc + (hBase - smb) + 2 * (r0 * LDH + n)) = __floats2half2_rn(v0, v1);
                *(__half2*)(smc + (hBase - smb) + 2 * (r1 * LDH + n)) = __floats2half2_rn(v2, v3);
            }
        }
        GBAR(barId);

        // ---------- GEMM2: D2 = H(128) @ W2 ----------
#pragma unroll
        for (int j = 0; j < 8; ++j)
#pragma unroll
            for (int q = 0; q < 4; ++q) acc[j][q] = 0.f;

#pragma unroll
        for (int ks = 0; ks < 8; ++ks) {
            const uint32_t kOff = (uint32_t)(ks * 16) * 2;
            uint32_t a[4];
            ldsm_x4(a[0], a[1], a[2], a[3], hBase + hRowOff + kOff);
#pragma unroll
            for (int jj = 0; jj < 4; ++jj) {
                const uint32_t nOff = (uint32_t)((nbase + jj * 16) * LDH) * 2;
                uint32_t bh[4], bl[4];
                ldsm_x4(bh[0], bh[1], bh[2], bh[3], smb + SM_W2_HI + b2LaneOff + nOff + kOff);
                ldsm_x4(bl[0], bl[1], bl[2], bl[3], smb + SM_W2_LO + b2LaneOff + nOff + kOff);
                mma_f16(acc[2 * jj],     a, bh);
                mma_f16(acc[2 * jj + 1], a, bh + 2);
                mma_f16(acc[2 * jj],     a, bl);
                mma_f16(acc[2 * jj + 1], a, bl + 2);
            }
        }

        // ---------- epilogue 2: scatter ----------
        {
            int tg0 = tgts[m0 + crow];
            int tg1 = tgts[m0 + crow + 8];
            size_t ga0 = __cvta_generic_to_global(&g_agg[(size_t)tg0 * 128]);
            size_t ga1 = __cvta_generic_to_global(&g_agg[(size_t)tg1 * 128]);
#pragma unroll
            for (int j = 0; j < 8; ++j) {
                int n = nbase + j * 8 + ccol;
                float v0 = acc[j][0] + b2s[n];
                float v1 = acc[j][1] + b2s[n + 1];
                float v2 = acc[j][2] + b2s[n];
                float v3 = acc[j][3] + b2s[n + 1];
                asm volatile("red.global.add.v2.f32 [%0], {%1,%2};"
                             :: "l"(ga0 + (size_t)n * 4), "f"(v0), "f"(v1) : "memory");
                asm volatile("red.global.add.v2.f32 [%0], {%1,%2};"
                             :: "l"(ga1 + (size_t)n * 4), "f"(v2), "f"(v3) : "memory");
            }
        }
        GBAR(barId);
        buf ^= 1;
    }
}

// ================= NODE KERNEL (mma.sync f16 hybrid) =================
#define NLDB 136
#define NB_HI 0
#define NB_LO 34816
#define NVS   69632
#define NMS   87040
#define NODE_SMEM_BYTES 104448

__device__ __forceinline__ void hgemm_128(uint32_t smb, uint32_t aAddr,
                                          uint32_t bHiOff, uint32_t bLoOff,
                                          uint32_t bLaneOff, int nbase, float acc[8][4]) {
#pragma unroll
    for (int j = 0; j < 8; ++j)
#pragma unroll
        for (int q = 0; q < 4; ++q) acc[j][q] = 0.f;
#pragma unroll
    for (int ks = 0; ks < 8; ++ks) {
        const uint32_t kOff = (uint32_t)(ks * 16) * 2;
        uint32_t a[4];
        ldsm_x4(a[0], a[1], a[2], a[3], aAddr + kOff);
#pragma unroll
        for (int jj = 0; jj < 4; ++jj) {
            const uint32_t nOff = (uint32_t)((nbase + jj * 16) * NLDB) * 2;
            uint32_t bh[4], bl[4];
            ldsm_x4(bh[0], bh[1], bh[2], bh[3], smb + bHiOff + bLaneOff + nOff + kOff);
            ldsm_x4(bl[0], bl[1], bl[2], bl[3], smb + bLoOff + bLaneOff + nOff + kOff);
            mma_f16(acc[2 * jj],     a, bh);
            mma_f16(acc[2 * jj + 1], a, bh + 2);
            mma_f16(acc[2 * jj],     a, bl);
            mma_f16(acc[2 * jj + 1], a, bl + 2);
        }
    }
}

__device__ __forceinline__ void node_stageB(char* smc, const float* __restrict__ src, int tid) {
    for (int idx = tid; idx < 128 * 64; idx += 256) {
        int n = idx >> 6, kp = idx & 63;
        float v0 = __ldg(&src[n * 128 + 2 * kp]);
        float v1 = __ldg(&src[n * 128 + 2 * kp + 1]);
        __half h0, l0, h1, l1;
        fsplit(v0, h0, l0);
        fsplit(v1, h1, l1);
        *(__half2*)(smc + NB_HI + 2 * (n * NLDB + 2 * kp)) = __halves2half2(h0, h1);
        *(__half2*)(smc + NB_LO + 2 * (n * NLDB + 2 * kp)) = __halves2half2(l0, l1);
    }
}

__global__ __launch_bounds__(256)
void node_kernel(const float* __restrict__ wih, const float* __restrict__ bih,
                 const float* __restrict__ bhh, const float* __restrict__ ow,
                 const float* __restrict__ ob, float* __restrict__ out)
{
    extern __shared__ char smc[];
    const uint32_t smb = smem_u32(smc);
    const int tid = threadIdx.x, wid = tid >> 5, lane = tid & 31;
    const int m0 = (wid & 3) * 16, nbase = (wid >> 2) * 64;
    const int base = blockIdx.x * 64;
    const int crow = lane >> 2, ccol = (lane & 3) * 2;

    // ---- V tile (mean-aggregated, f16) ----
    for (int idx = tid; idx < 64 * 64; idx += 256) {
        int m = idx >> 6, kp = idx & 63;
        int nd = base + m;
        float a0 = 0.f, a1 = 0.f;
        if (nd < NN) {
            float inv = 1.0f / fmaxf(g_cnt[nd], 1.0f);
            a0 = g_agg[(size_t)nd * 128 + 2 * kp] * inv;
            a1 = g_agg[(size_t)nd * 128 + 2 * kp + 1] * inv;
        }
        *(__half2*)(smc + NVS + 2 * (m * NLDB + 2 * kp)) = __floats2half2_rn(a0, a1);
    }

    const uint32_t aRow = (uint32_t)((m0 + (lane & 15)) * NLDB + ((lane >> 4) << 3)) * 2;
    const uint32_t bRow = (uint32_t)((lane & 7) + ((lane >> 4) << 3));
    const uint32_t bLane = (uint32_t)(bRow * NLDB + (((lane >> 3) & 1) << 3)) * 2;

    float acc[8][4], rg[8][4], ng[8][4];

    // ---- r gate ----
    node_stageB(smc, wih, tid);
    __syncthreads();
    hgemm_128(smb, smb + NVS + aRow, NB_HI, NB_LO, bLane, nbase, acc);
#pragma unroll
    for (int j = 0; j < 8; ++j) {
        int n = nbase + j * 8 + ccol;
        rg[j][0] = sigm(acc[j][0] + __ldg(&bih[n])     + __ldg(&bhh[n]));
        rg[j][1] = sigm(acc[j][1] + __ldg(&bih[n + 1]) + __ldg(&bhh[n + 1]));
        rg[j][2] = sigm(acc[j][2] + __ldg(&bih[n])     + __ldg(&bhh[n]));
        rg[j][3] = sigm(acc[j][3] + __ldg(&bih[n + 1]) + __ldg(&bhh[n + 1]));
    }
    __syncthreads();

    // ---- n gate (rows [256,384)): n = tanh(i_n + r * b_hh_n) ----
    node_stageB(smc, wih + 2 * 128 * 128, tid);
    __syncthreads();
    hgemm_128(smb, smb + NVS + aRow, NB_HI, NB_LO, bLane, nbase, acc);
#pragma unroll
    for (int j = 0; j < 8; ++j) {
        int n = 256 + nbase + j * 8 + ccol;
        ng[j][0] = tanhf(acc[j][0] + __ldg(&bih[n])     + rg[j][0] * __ldg(&bhh[n]));
        ng[j][1] = tanhf(acc[j][1] + __ldg(&bih[n + 1]) + rg[j][1] * __ldg(&bhh[n + 1]));
        ng[j][2] = tanhf(acc[j][2] + __ldg(&bih[n])     + rg[j][2] * __ldg(&bhh[n]));
        ng[j][3] = tanhf(acc[j][3] + __ldg(&bih[n + 1]) + rg[j][3] * __ldg(&bhh[n + 1]));
    }
    __syncthreads();

    // ---- z gate (rows [128,256)) + memory = (1-z)*n -> Ms (f16) ----
    node_stageB(smc, wih + 1 * 128 * 128, tid);
    __syncthreads();
    hgemm_128(smb, smb + NVS + aRow, NB_HI, NB_LO, bLane, nbase, acc);
    {
        int r0 = m0 + crow, r1 = m0 + crow + 8;
#pragma unroll
        for (int j = 0; j < 8; ++j) {
            int nl = nbase + j * 8 + ccol;
            int n = 128 + nl;
            float z0 = sigm(acc[j][0] + __ldg(&bih[n])     + __ldg(&bhh[n]));
            float z1 = sigm(acc[j][1] + __ldg(&bih[n + 1]) + __ldg(&bhh[n + 1]));
            float z2 = sigm(acc[j][2] + __ldg(&bih[n])     + __ldg(&bhh[n]));
            float z3 = sigm(acc[j][3] + __ldg(&bih[n + 1]) + __ldg(&bhh[n + 1]));
            float m0v = (1.f - z0) * ng[j][0];
            float m1v = (1.f - z1) * ng[j][1];
            float m2v = (1.f - z2) * ng[j][2];
            float m3v = (1.f - z3) * ng[j][3];
            *(__half2*)(smc + NMS + 2 * (r0 * NLDB + nl)) = __floats2half2_rn(m0v, m1v);
            *(__half2*)(smc + NMS + 2 * (r1 * NLDB + nl)) = __floats2half2_rn(m2v, m3v);
        }
    }
    __syncthreads();

    // ---- out = memory @ out_w^T + out_b ----
    node_stageB(smc, ow, tid);
    __syncthreads();
    hgemm_128(smb, smb + NMS + aRow, NB_HI, NB_LO, bLane, nbase, acc);
    {
        int r0 = m0 + crow, r1 = m0 + crow + 8;
        int nd0 = base + r0, nd1 = base + r1;
#pragma unroll
        for (int j = 0; j < 8; ++j) {
            int n = nbase + j * 8 + ccol;
            float o0 = __ldg(&ob[n]), o1 = __ldg(&ob[n + 1]);
            if (nd0 < NN)
                *(float2*)&out[(size_t)nd0 * 128 + n] = make_float2(acc[j][0] + o0, acc[j][1] + o1);
            if (nd1 < NN)
                *(float2*)&out[(size_t)nd1 * 128 + n] = make_float2(acc[j][2] + o0, acc[j][3] + o1);
        }
    }
}

// ================= launch =================
extern "C" void kernel_launch(void* const* d_in, const int* in_sizes, int n_in,
                              void* d_out, int out_size) {
    const float* x     = (const float*)d_in[0];
    const float* eattr = (const float*)d_in[1];
    const float* t     = (const float*)d_in[2];
    const float* tw    = (const float*)d_in[3];
    const float* tb    = (const float*)d_in[4];
    const float* w1    = (const float*)d_in[5];
    const float* b1    = (const float*)d_in[6];
    const float* w2    = (const float*)d_in[7];
    const float* b2    = (const float*)d_in[8];
    const float* wih   = (const float*)d_in[9];
    const float* bih   = (const float*)d_in[11];
    const float* bhh   = (const float*)d_in[12];
    const float* ow    = (const float*)d_in[13];
    const float* ob    = (const float*)d_in[14];
    const int*   ei    = (const int*)d_in[15];
    float* out = (float*)d_out;

    cudaFuncSetAttribute(edge_kernel, cudaFuncAttributeMaxDynamicSharedMemorySize, EDGE_SMEM_BYTES);
    cudaFuncSetAttribute(node_kernel, cudaFuncAttributeMaxDynamicSharedMemorySize, NODE_SMEM_BYTES);

    zero_kernel<<<256, 256>>>();
    split_x_kernel<<<(NN * 64 + 255) / 256, 256>>>(x);
    edge_pre_kernel<<<(NE + 255) / 256, 256>>>(eattr, t, tw, tb, ei);
    edge_kernel<<<148, 256, EDGE_SMEM_BYTES>>>(w1, b1, w2, b2, ei);
    node_kernel<<<(NN + 63) / 64, 256, NODE_SMEM_BYTES>>>(wih, bih, bhh, ow, ob, out);
}

// round 7
// speedup vs baseline: 8.1022x; 1.2387x over previous
#include <cuda_runtime.h>
#include <cuda_bf16.h>
#include <cuda_fp16.h>
#include <math.h>
#include <stdint.h>

#define NN 50000
#define NE 800000
#define NODE_F 128
#define EDGE_F 32
#define TIME_D 16
#define K1 176
#define DN 128

typedef unsigned long long ull;

// ---------------- scratch ----------------
__device__ float g_agg[(size_t)NN * 128];
__device__ float g_cnt[NN];
__device__ uint32_t g_xf16[(size_t)NN * 64];       // x as f16x2
__device__ uint32_t g_tf16[(size_t)NE * 24];       // tail (attr|time) as f16x2, 48 vals

// ---------------- helpers ----------------
__device__ __forceinline__ uint32_t smem_u32(const void* p) {
    uint32_t a;
    asm("{ .reg .u64 t; cvta.to.shared.u64 t, %1; cvt.u32.u64 %0, t; }" : "=r"(a) : "l"(p));
    return a;
}
__device__ __forceinline__ float sigm(float x) { return 1.0f / (1.0f + expf(-x)); }

__device__ __forceinline__ uint32_t h2u(float a, float b) {
    __half2 h = __floats2half2_rn(a, b);
    return *reinterpret_cast<uint32_t*>(&h);
}
__device__ __forceinline__ void fsplit(float v, __half& h, __half& l) {
    h = __float2half_rn(v);
    l = __float2half_rn(v - __half2float(h));
}

__device__ __forceinline__ void ldsm_x4(uint32_t& r0, uint32_t& r1, uint32_t& r2, uint32_t& r3,
                                        uint32_t addr) {
    asm volatile("ldmatrix.sync.aligned.m8n8.x4.shared.b16 {%0,%1,%2,%3}, [%4];"
                 : "=r"(r0), "=r"(r1), "=r"(r2), "=r"(r3) : "r"(addr));
}
__device__ __forceinline__ void mma_f16(float* d, const uint32_t* a, const uint32_t* b) {
    asm volatile("mma.sync.aligned.m16n8k16.row.col.f32.f16.f16.f32 "
                 "{%0,%1,%2,%3}, {%4,%5,%6,%7}, {%8,%9}, {%0,%1,%2,%3};"
                 : "+f"(d[0]), "+f"(d[1]), "+f"(d[2]), "+f"(d[3])
                 : "r"(a[0]), "r"(a[1]), "r"(a[2]), "r"(a[3]), "r"(b[0]), "r"(b[1]));
}
__device__ __forceinline__ void cp16(uint32_t s, const void* g) {
    asm volatile("cp.async.ca.shared.global [%0], [%1], 16;" :: "r"(s), "l"(g));
}
#define CP_COMMIT() asm volatile("cp.async.commit_group;" ::: "memory")
#define CP_WAIT1()  asm volatile("cp.async.wait_group 1;" ::: "memory")
#define GBAR(id)    asm volatile("bar.sync %0, 128;" :: "r"(id) : "memory")

// ---------------- zero scratch ----------------
__global__ void zero_kernel() {
    int i = blockIdx.x * blockDim.x + threadIdx.x;
    int stride = gridDim.x * blockDim.x;
    float4 z = make_float4(0.f, 0.f, 0.f, 0.f);
    float4* a4 = reinterpret_cast<float4*>(g_agg);
    for (int j = i; j < NN * 128 / 4; j += stride) a4[j] = z;
    for (int j = i; j < NN; j += stride) g_cnt[j] = 0.f;
}

// ---------------- precompute: x -> f16 ----------------
__global__ void split_x_kernel(const float* __restrict__ x) {
    int i = blockIdx.x * blockDim.x + threadIdx.x;
    if (i < NN * 64) {
        float2 f = __ldg(&((const float2*)x)[i]);
        g_xf16[i] = h2u(f.x, f.y);
    }
}

// ---------------- precompute: per-edge tail + cnt ----------------
__global__ void edge_pre_kernel(const float* __restrict__ eattr, const float* __restrict__ tt,
                                const float* __restrict__ tw, const float* __restrict__ tb,
                                const int* __restrict__ ei) {
    int e = blockIdx.x * blockDim.x + threadIdx.x;
    if (e >= NE) return;
    uint32_t th[24];
    const float4* er = (const float4*)(eattr + (size_t)e * 32);
#pragma unroll
    for (int i = 0; i < 8; ++i) {
        float4 f = __ldg(&er[i]);
        th[2 * i]     = h2u(f.x, f.y);
        th[2 * i + 1] = h2u(f.z, f.w);
    }
    float tv = __ldg(&tt[e]);
#pragma unroll
    for (int d = 0; d < 8; ++d) {
        float a = cosf(tv * __ldg(&tw[2 * d])     + __ldg(&tb[2 * d]));
        float b = cosf(tv * __ldg(&tw[2 * d + 1]) + __ldg(&tb[2 * d + 1]));
        th[16 + d] = h2u(a, b);
    }
    uint4* dh = (uint4*)(g_tf16 + (size_t)e * 24);
#pragma unroll
    for (int q = 0; q < 6; ++q)
        dh[q] = make_uint4(th[4 * q], th[4 * q + 1], th[4 * q + 2], th[4 * q + 3]);
    atomicAdd(&g_cnt[__ldg(&ei[NE + e])], 1.0f);
}

// ================= EDGE KERNEL (pure f16, m32n32 warps) =================
#define EK_M   32
#define NT32   (NE / EK_M)
#define LDA    184
#define LDH    136
#define A_BYTES 11776      // 32*184*2

// smem byte offsets
#define SM_W1     0        // [128][184] f16 = 47104
#define SM_W2     47104    // [128][136] f16 = 34816
#define SM_A      81920    // 4 buffers of A_BYTES (group*2+buf)
#define SM_H      129024   // 2 groups of 8704
#define SM_B1     146432
#define SM_B2     146944
#define SM_TGT    147456   // (group*2+buf)*32 ints
#define EDGE_SMEM_BYTES 147968

__device__ __forceinline__ void prefetch_tile(int tile, uint32_t aBase, int* tgtS,
                                              const int* __restrict__ ei, int gt) {
    const int e = gt >> 2, sub = gt & 3;
    const int ge = tile * EK_M + e;
    const int src = __ldg(&ei[ge]);
    const char* xf = (const char*)g_xf16 + (size_t)src * 256;
    const char* tf = (const char*)g_tf16 + (size_t)ge * 96;
    const uint32_t arow = aBase + (uint32_t)e * (LDA * 2);
#pragma unroll
    for (int c = sub; c < 16; c += 4) cp16(arow + c * 16, xf + c * 16);
#pragma unroll
    for (int c = sub; c < 6; c += 4)  cp16(arow + 256 + c * 16, tf + c * 16);
    if (sub == 0) tgtS[e] = __ldg(&ei[NE + ge]);
}

__global__ __launch_bounds__(256, 1)
void edge_kernel(const float* __restrict__ w1, const float* __restrict__ b1,
                 const float* __restrict__ w2, const float* __restrict__ b2,
                 const int* __restrict__ ei)
{
    extern __shared__ char smc[];
    const uint32_t smb = smem_u32(smc);
    const int tid = threadIdx.x;
    const int wid = tid >> 5, lane = tid & 31;
    const int half = wid >> 2;           // ping-pong group 0/1
    const int gw = wid & 3;              // warp within group
    const int nbase = gw * 32;           // 32-col slice per warp
    const int gt = tid & 127;

    float* b1s = (float*)(smc + SM_B1);
    float* b2s = (float*)(smc + SM_B2);

    // ---- stage weights (single f16, [n][k]) ----
    for (int idx = tid; idx < K1 * DN; idx += 256) {
        int k = idx >> 7, n = idx & 127;
        *(__half*)(smc + SM_W1 + 2 * (n * LDA + k)) = __float2half_rn(w1[idx]);
    }
    for (int idx = tid; idx < DN * DN; idx += 256) {
        int k = idx >> 7, n = idx & 127;
        *(__half*)(smc + SM_W2 + 2 * (n * LDH + k)) = __float2half_rn(w2[idx]);
    }
    for (int i = tid; i < 128; i += 256) { b1s[i] = b1[i]; b2s[i] = b2[i]; }
    __syncthreads();

    const int barId = 1 + half;
    const uint32_t hBase = smb + SM_H + half * 8704;

    // fragment lane addressing (bytes)
    const uint32_t aRow0 = (uint32_t)((lane & 15) * LDA + ((lane >> 4) << 3)) * 2;
    const uint32_t aRow1 = aRow0 + (uint32_t)(16 * LDA) * 2;
    const uint32_t hRow0 = (uint32_t)((lane & 15) * LDH + ((lane >> 4) << 3)) * 2;
    const uint32_t hRow1 = hRow0 + (uint32_t)(16 * LDH) * 2;
    const uint32_t bRow = (uint32_t)((lane & 7) + ((lane >> 4) << 3));
    const uint32_t bColPiece = (uint32_t)(((lane >> 3) & 1) << 3);
    const uint32_t b1LaneOff = (uint32_t)(bRow * LDA + bColPiece) * 2;
    const uint32_t b2LaneOff = (uint32_t)(bRow * LDH + bColPiece) * 2;
    const int crow = lane >> 2;
    const int ccol = (lane & 3) * 2;

    int buf = 0;
    int tile = blockIdx.x * 2 + half;
    const int step = gridDim.x * 2;

    if (tile < NT32)
        prefetch_tile(tile, smb + SM_A + (uint32_t)(half * 2 + buf) * A_BYTES,
                      (int*)(smc + SM_TGT) + (half * 2 + buf) * 32, ei, gt);
    CP_COMMIT();

    for (; tile < NT32; tile += step) {
        const int nxt = tile + step;
        if (nxt < NT32)
            prefetch_tile(nxt, smb + SM_A + (uint32_t)(half * 2 + (buf ^ 1)) * A_BYTES,
                          (int*)(smc + SM_TGT) + (half * 2 + (buf ^ 1)) * 32, ei, gt);
        CP_COMMIT();
        CP_WAIT1();
        GBAR(barId);

        const uint32_t aBase = smb + SM_A + (uint32_t)(half * 2 + buf) * A_BYTES;
        int* tgts = (int*)(smc + SM_TGT) + (half * 2 + buf) * 32;

        // acc[mf][piece][quad] : mf = m16-frag (rows mf*16..), piece = n8 (cols nbase+piece*8)
        float acc[2][4][4];
#pragma unroll
        for (int i = 0; i < 2; ++i)
#pragma unroll
            for (int j = 0; j < 4; ++j)
#pragma unroll
                for (int q = 0; q < 4; ++q) acc[i][j][q] = 0.f;

        // ---------- GEMM1: D1 = A(176) @ W1 ----------
#pragma unroll
        for (int ks = 0; ks < 11; ++ks) {
            const uint32_t kOff = (uint32_t)(ks * 16) * 2;
            uint32_t a0[4], a1[4];
            ldsm_x4(a0[0], a0[1], a0[2], a0[3], aBase + aRow0 + kOff);
            ldsm_x4(a1[0], a1[1], a1[2], a1[3], aBase + aRow1 + kOff);
#pragma unroll
            for (int jj = 0; jj < 2; ++jj) {
                const uint32_t nOff = (uint32_t)((nbase + jj * 16) * LDA) * 2;
                uint32_t b[4];
                ldsm_x4(b[0], b[1], b[2], b[3], smb + SM_W1 + b1LaneOff + nOff + kOff);
                mma_f16(acc[0][jj * 2],     a0, b);
                mma_f16(acc[0][jj * 2 + 1], a0, b + 2);
                mma_f16(acc[1][jj * 2],     a1, b);
                mma_f16(acc[1][jj * 2 + 1], a1, b + 2);
            }
        }

        // ---------- epilogue 1: relu(D1 + b1) -> H (f16) ----------
#pragma unroll
        for (int mf = 0; mf < 2; ++mf) {
            int r0 = mf * 16 + crow, r1 = r0 + 8;
#pragma unroll
            for (int j = 0; j < 4; ++j) {
                int n = nbase + j * 8 + ccol;
                float v0 = fmaxf(acc[mf][j][0] + b1s[n],     0.f);
                float v1 = fmaxf(acc[mf][j][1] + b1s[n + 1], 0.f);
                float v2 = fmaxf(acc[mf][j][2] + b1s[n],     0.f);
                float v3 = fmaxf(acc[mf][j][3] + b1s[n + 1], 0.f);
                *(__half2*)(smc + (hBase - smb) + 2 * (r0 * LDH + n)) = __floats2half2_rn(v0, v1);
                *(__half2*)(smc + (hBase - smb) + 2 * (r1 * LDH + n)) = __floats2half2_rn(v2, v3);
            }
        }
        GBAR(barId);

        // ---------- GEMM2: D2 = H(128) @ W2 ----------
#pragma unroll
        for (int i = 0; i < 2; ++i)
#pragma unroll
            for (int j = 0; j < 4; ++j)
#pragma unroll
                for (int q = 0; q < 4; ++q) acc[i][j][q] = 0.f;

#pragma unroll
        for (int ks = 0; ks < 8; ++ks) {
            const uint32_t kOff = (uint32_t)(ks * 16) * 2;
            uint32_t a0[4], a1[4];
            ldsm_x4(a0[0], a0[1], a0[2], a0[3], hBase + hRow0 + kOff);
            ldsm_x4(a1[0], a1[1], a1[2], a1[3], hBase + hRow1 + kOff);
#pragma unroll
            for (int jj = 0; jj < 2; ++jj) {
                const uint32_t nOff = (uint32_t)((nbase + jj * 16) * LDH) * 2;
                uint32_t b[4];
                ldsm_x4(b[0], b[1], b[2], b[3], smb + SM_W2 + b2LaneOff + nOff + kOff);
                mma_f16(acc[0][jj * 2],     a0, b);
                mma_f16(acc[0][jj * 2 + 1], a0, b + 2);
                mma_f16(acc[1][jj * 2],     a1, b);
                mma_f16(acc[1][jj * 2 + 1], a1, b + 2);
            }
        }

        // ---------- epilogue 2: scatter ----------
#pragma unroll
        for (int mf = 0; mf < 2; ++mf) {
            int tg0 = tgts[mf * 16 + crow];
            int tg1 = tgts[mf * 16 + crow + 8];
            size_t ga0 = __cvta_generic_to_global(&g_agg[(size_t)tg0 * 128]);
            size_t ga1 = __cvta_generic_to_global(&g_agg[(size_t)tg1 * 128]);
#pragma unroll
            for (int j = 0; j < 4; ++j) {
                int n = nbase + j * 8 + ccol;
                float v0 = acc[mf][j][0] + b2s[n];
                float v1 = acc[mf][j][1] + b2s[n + 1];
                float v2 = acc[mf][j][2] + b2s[n];
                float v3 = acc[mf][j][3] + b2s[n + 1];
                asm volatile("red.global.add.v2.f32 [%0], {%1,%2};"
                             :: "l"(ga0 + (size_t)n * 4), "f"(v0), "f"(v1) : "memory");
                asm volatile("red.global.add.v2.f32 [%0], {%1,%2};"
                             :: "l"(ga1 + (size_t)n * 4), "f"(v2), "f"(v3) : "memory");
            }
        }
        GBAR(barId);
        buf ^= 1;
    }
}

// ================= NODE KERNEL (unchanged from R6, f16 hybrid hi/lo) =================
#define NLDB 136
#define NB_HI 0
#define NB_LO 34816
#define NVS   69632
#define NMS   87040
#define NODE_SMEM_BYTES 104448

__device__ __forceinline__ void hgemm_128(uint32_t smb, uint32_t aAddr,
                                          uint32_t bHiOff, uint32_t bLoOff,
                                          uint32_t bLaneOff, int nbase, float acc[8][4]) {
#pragma unroll
    for (int j = 0; j < 8; ++j)
#pragma unroll
        for (int q = 0; q < 4; ++q) acc[j][q] = 0.f;
#pragma unroll
    for (int ks = 0; ks < 8; ++ks) {
        const uint32_t kOff = (uint32_t)(ks * 16) * 2;
        uint32_t a[4];
        ldsm_x4(a[0], a[1], a[2], a[3], aAddr + kOff);
#pragma unroll
        for (int jj = 0; jj < 4; ++jj) {
            const uint32_t nOff = (uint32_t)((nbase + jj * 16) * NLDB) * 2;
            uint32_t bh[4], bl[4];
            ldsm_x4(bh[0], bh[1], bh[2], bh[3], smb + bHiOff + bLaneOff + nOff + kOff);
            ldsm_x4(bl[0], bl[1], bl[2], bl[3], smb + bLoOff + bLaneOff + nOff + kOff);
            mma_f16(acc[2 * jj],     a, bh);
            mma_f16(acc[2 * jj + 1], a, bh + 2);
            mma_f16(acc[2 * jj],     a, bl);
            mma_f16(acc[2 * jj + 1], a, bl + 2);
        }
    }
}

__device__ __forceinline__ void node_stageB(char* smc, const float* __restrict__ src, int tid) {
    for (int idx = tid; idx < 128 * 64; idx += 256) {
        int n = idx >> 6, kp = idx & 63;
        float v0 = __ldg(&src[n * 128 + 2 * kp]);
        float v1 = __ldg(&src[n * 128 + 2 * kp + 1]);
        __half h0, l0, h1, l1;
        fsplit(v0, h0, l0);
        fsplit(v1, h1, l1);
        *(__half2*)(smc + NB_HI + 2 * (n * NLDB + 2 * kp)) = __halves2half2(h0, h1);
        *(__half2*)(smc + NB_LO + 2 * (n * NLDB + 2 * kp)) = __halves2half2(l0, l1);
    }
}

__global__ __launch_bounds__(256)
void node_kernel(const float* __restrict__ wih, const float* __restrict__ bih,
                 const float* __restrict__ bhh, const float* __restrict__ ow,
                 const float* __restrict__ ob, float* __restrict__ out)
{
    extern __shared__ char smc[];
    const uint32_t smb = smem_u32(smc);
    const int tid = threadIdx.x, wid = tid >> 5, lane = tid & 31;
    const int m0 = (wid & 3) * 16, nbase = (wid >> 2) * 64;
    const int base = blockIdx.x * 64;
    const int crow = lane >> 2, ccol = (lane & 3) * 2;

    // ---- V tile (mean-aggregated, f16) ----
    for (int idx = tid; idx < 64 * 64; idx += 256) {
        int m = idx >> 6, kp = idx & 63;
        int nd = base + m;
        float a0 = 0.f, a1 = 0.f;
        if (nd < NN) {
            float inv = 1.0f / fmaxf(g_cnt[nd], 1.0f);
            a0 = g_agg[(size_t)nd * 128 + 2 * kp] * inv;
            a1 = g_agg[(size_t)nd * 128 + 2 * kp + 1] * inv;
        }
        *(__half2*)(smc + NVS + 2 * (m * NLDB + 2 * kp)) = __floats2half2_rn(a0, a1);
    }

    const uint32_t aRow = (uint32_t)((m0 + (lane & 15)) * NLDB + ((lane >> 4) << 3)) * 2;
    const uint32_t bRow = (uint32_t)((lane & 7) + ((lane >> 4) << 3));
    const uint32_t bLane = (uint32_t)(bRow * NLDB + (((lane >> 3) & 1) << 3)) * 2;

    float acc[8][4], rg[8][4], ng[8][4];

    // ---- r gate ----
    node_stageB(smc, wih, tid);
    __syncthreads();
    hgemm_128(smb, smb + NVS + aRow, NB_HI, NB_LO, bLane, nbase, acc);
#pragma unroll
    for (int j = 0; j < 8; ++j) {
        int n = nbase + j * 8 + ccol;
        rg[j][0] = sigm(acc[j][0] + __ldg(&bih[n])     + __ldg(&bhh[n]));
        rg[j][1] = sigm(acc[j][1] + __ldg(&bih[n + 1]) + __ldg(&bhh[n + 1]));
        rg[j][2] = sigm(acc[j][2] + __ldg(&bih[n])     + __ldg(&bhh[n]));
        rg[j][3] = sigm(acc[j][3] + __ldg(&bih[n + 1]) + __ldg(&bhh[n + 1]));
    }
    __syncthreads();

    // ---- n gate ----
    node_stageB(smc, wih + 2 * 128 * 128, tid);
    __syncthreads();
    hgemm_128(smb, smb + NVS + aRow, NB_HI, NB_LO, bLane, nbase, acc);
#pragma unroll
    for (int j = 0; j < 8; ++j) {
        int n = 256 + nbase + j * 8 + ccol;
        ng[j][0] = tanhf(acc[j][0] + __ldg(&bih[n])     + rg[j][0] * __ldg(&bhh[n]));
        ng[j][1] = tanhf(acc[j][1] + __ldg(&bih[n + 1]) + rg[j][1] * __ldg(&bhh[n + 1]));
        ng[j][2] = tanhf(acc[j][2] + __ldg(&bih[n])     + rg[j][2] * __ldg(&bhh[n]));
        ng[j][3] = tanhf(acc[j][3] + __ldg(&bih[n + 1]) + rg[j][3] * __ldg(&bhh[n + 1]));
    }
    __syncthreads();

    // ---- z gate + memory ----
    node_stageB(smc, wih + 1 * 128 * 128, tid);
    __syncthreads();
    hgemm_128(smb, smb + NVS + aRow, NB_HI, NB_LO, bLane, nbase, acc);
    {
        int r0 = m0 + crow, r1 = m0 + crow + 8;
#pragma unroll
        for (int j = 0; j < 8; ++j) {
            int nl = nbase + j * 8 + ccol;
            int n = 128 + nl;
            float z0 = sigm(acc[j][0] + __ldg(&bih[n])     + __ldg(&bhh[n]));
            float z1 = sigm(acc[j][1] + __ldg(&bih[n + 1]) + __ldg(&bhh[n + 1]));
            float z2 = sigm(acc[j][2] + __ldg(&bih[n])     + __ldg(&bhh[n]));
            float z3 = sigm(acc[j][3] + __ldg(&bih[n + 1]) + __ldg(&bhh[n + 1]));
            float m0v = (1.f - z0) * ng[j][0];
            float m1v = (1.f - z1) * ng[j][1];
            float m2v = (1.f - z2) * ng[j][2];
            float m3v = (1.f - z3) * ng[j][3];
            *(__half2*)(smc + NMS + 2 * (r0 * NLDB + nl)) = __floats2half2_rn(m0v, m1v);
            *(__half2*)(smc + NMS + 2 * (r1 * NLDB + nl)) = __floats2half2_rn(m2v, m3v);
        }
    }
    __syncthreads();

    // ---- out projection ----
    node_stageB(smc, ow, tid);
    __syncthreads();
    hgemm_128(smb, smb + NMS + aRow, NB_HI, NB_LO, bLane, nbase, acc);
    {
        int r0 = m0 + crow, r1 = m0 + crow + 8;
        int nd0 = base + r0, nd1 = base + r1;
#pragma unroll
        for (int j = 0; j < 8; ++j) {
            int n = nbase + j * 8 + ccol;
            float o0 = __ldg(&ob[n]), o1 = __ldg(&ob[n + 1]);
            if (nd0 < NN)
                *(float2*)&out[(size_t)nd0 * 128 + n] = make_float2(acc[j][0] + o0, acc[j][1] + o1);
            if (nd1 < NN)
                *(float2*)&out[(size_t)nd1 * 128 + n] = make_float2(acc[j][2] + o0, acc[j][3] + o1);
        }
    }
}

// ================= launch =================
extern "C" void kernel_launch(void* const* d_in, const int* in_sizes, int n_in,
                              void* d_out, int out_size) {
    const float* x     = (const float*)d_in[0];
    const float* eattr = (const float*)d_in[1];
    const float* t     = (const float*)d_in[2];
    const float* tw    = (const float*)d_in[3];
    const float* tb    = (const float*)d_in[4];
    const float* w1    = (const float*)d_in[5];
    const float* b1    = (const float*)d_in[6];
    const float* w2    = (const float*)d_in[7];
    const float* b2    = (const float*)d_in[8];
    const float* wih   = (const float*)d_in[9];
    const float* bih   = (const float*)d_in[11];
    const float* bhh   = (const float*)d_in[12];
    const float* ow    = (const float*)d_in[13];
    const float* ob    = (const float*)d_in[14];
    const int*   ei    = (const int*)d_in[15];
    float* out = (float*)d_out;

    cudaFuncSetAttribute(edge_kernel, cudaFuncAttributeMaxDynamicSharedMemorySize, EDGE_SMEM_BYTES);
    cudaFuncSetAttribute(node_kernel, cudaFuncAttributeMaxDynamicSharedMemorySize, NODE_SMEM_BYTES);

    zero_kernel<<<256, 256>>>();
    split_x_kernel<<<(NN * 64 + 255) / 256, 256>>>(x);
    edge_pre_kernel<<<(NE + 255) / 256, 256>>>(eattr, t, tw, tb, ei);
    edge_kernel<<<148, 256, EDGE_SMEM_BYTES>>>(w1, b1, w2, b2, ei);
    node_kernel<<<(NN + 63) / 64, 256, NODE_SMEM_BYTES>>>(wih, bih, bhh, ow, ob, out);
}

// round 8
// speedup vs baseline: 9.1802x; 1.1330x over previous
#include <cuda_runtime.h>
#include <cuda_bf16.h>
#include <cuda_fp16.h>
#include <math.h>
#include <stdint.h>

#define NN 50000
#define NE 800000
#define NODE_F 128
#define EDGE_F 32
#define TIME_D 16
#define K1 176
#define DN 128

typedef unsigned long long ull;

// ---------------- scratch ----------------
__device__ float g_agg[(size_t)NN * 128];
__device__ float g_cnt[NN];
__device__ uint32_t g_yf16[(size_t)NN * 64];       // Y = x @ W1x, f16x2 packed
__device__ uint32_t g_tf16[(size_t)NE * 24];       // tail (attr|time) f16x2, 48 vals

// ---------------- helpers ----------------
__device__ __forceinline__ uint32_t smem_u32(const void* p) {
    uint32_t a;
    asm("{ .reg .u64 t; cvta.to.shared.u64 t, %1; cvt.u32.u64 %0, t; }" : "=r"(a) : "l"(p));
    return a;
}
__device__ __forceinline__ float sigm(float x) { return 1.0f / (1.0f + expf(-x)); }

__device__ __forceinline__ uint32_t h2u(float a, float b) {
    __half2 h = __floats2half2_rn(a, b);
    return *reinterpret_cast<uint32_t*>(&h);
}
__device__ __forceinline__ void fsplit(float v, __half& h, __half& l) {
    h = __float2half_rn(v);
    l = __float2half_rn(v - __half2float(h));
}

__device__ __forceinline__ void ldsm_x4(uint32_t& r0, uint32_t& r1, uint32_t& r2, uint32_t& r3,
                                        uint32_t addr) {
    asm volatile("ldmatrix.sync.aligned.m8n8.x4.shared.b16 {%0,%1,%2,%3}, [%4];"
                 : "=r"(r0), "=r"(r1), "=r"(r2), "=r"(r3) : "r"(addr));
}
__device__ __forceinline__ void mma_f16(float* d, const uint32_t* a, const uint32_t* b) {
    asm volatile("mma.sync.aligned.m16n8k16.row.col.f32.f16.f16.f32 "
                 "{%0,%1,%2,%3}, {%4,%5,%6,%7}, {%8,%9}, {%0,%1,%2,%3};"
                 : "+f"(d[0]), "+f"(d[1]), "+f"(d[2]), "+f"(d[3])
                 : "r"(a[0]), "r"(a[1]), "r"(a[2]), "r"(a[3]), "r"(b[0]), "r"(b[1]));
}
__device__ __forceinline__ void cp16(uint32_t s, const void* g) {
    asm volatile("cp.async.ca.shared.global [%0], [%1], 16;" :: "r"(s), "l"(g));
}
#define CP_COMMIT() asm volatile("cp.async.commit_group;" ::: "memory")
#define CP_WAIT1()  asm volatile("cp.async.wait_group 1;" ::: "memory")
#define GBAR(id)    asm volatile("bar.sync %0, 128;" :: "r"(id) : "memory")

// ---------------- zero scratch ----------------
__global__ void zero_kernel() {
    int i = blockIdx.x * blockDim.x + threadIdx.x;
    int stride = gridDim.x * blockDim.x;
    float4 z = make_float4(0.f, 0.f, 0.f, 0.f);
    float4* a4 = reinterpret_cast<float4*>(g_agg);
    for (int j = i; j < NN * 128 / 4; j += stride) a4[j] = z;
    for (int j = i; j < NN; j += stride) g_cnt[j] = 0.f;
}

// ---------------- precompute: per-edge tail + cnt ----------------
__global__ void edge_pre_kernel(const float* __restrict__ eattr, const float* __restrict__ tt,
                                const float* __restrict__ tw, const float* __restrict__ tb,
                                const int* __restrict__ ei) {
    int e = blockIdx.x * blockDim.x + threadIdx.x;
    if (e >= NE) return;
    uint32_t th[24];
    const float4* er = (const float4*)(eattr + (size_t)e * 32);
#pragma unroll
    for (int i = 0; i < 8; ++i) {
        float4 f = __ldg(&er[i]);
        th[2 * i]     = h2u(f.x, f.y);
        th[2 * i + 1] = h2u(f.z, f.w);
    }
    float tv = __ldg(&tt[e]);
#pragma unroll
    for (int d = 0; d < 8; ++d) {
        float a = cosf(tv * __ldg(&tw[2 * d])     + __ldg(&tb[2 * d]));
        float b = cosf(tv * __ldg(&tw[2 * d + 1]) + __ldg(&tb[2 * d + 1]));
        th[16 + d] = h2u(a, b);
    }
    uint4* dh = (uint4*)(g_tf16 + (size_t)e * 24);
#pragma unroll
    for (int q = 0; q < 6; ++q)
        dh[q] = make_uint4(th[4 * q], th[4 * q + 1], th[4 * q + 2], th[4 * q + 3]);
    atomicAdd(&g_cnt[__ldg(&ei[NE + e])], 1.0f);
}

// ================= Y KERNEL: Y = x @ W1[0:128,:] (f16) =================
#define YW 0          // [128][136] f16 = 34816
#define YA 34816      // [64][136]  f16 = 17408
#define Y_SMEM_BYTES 52352

__global__ __launch_bounds__(256)
void y_kernel(const float* __restrict__ x, const float* __restrict__ w1) {
    extern __shared__ char smc[];
    const uint32_t smb = smem_u32(smc);
    const int tid = threadIdx.x, wid = tid >> 5, lane = tid & 31;
    const int m0 = (wid & 3) * 16, nbase = (wid >> 2) * 64;
    const int base = blockIdx.x * 64;
    const int crow = lane >> 2, ccol = (lane & 3) * 2;

    // stage W1x [n][k]
    for (int idx = tid; idx < 128 * 128; idx += 256) {
        int k = idx >> 7, n = idx & 127;
        *(__half*)(smc + YW + 2 * (n * 136 + k)) = __float2half_rn(w1[k * 128 + n]);
    }
    // stage A = x rows (f16)
    for (int idx = tid; idx < 64 * 64; idx += 256) {
        int m = idx >> 6, kp = idx & 63;
        int row = base + m;
        uint32_t v = 0u;
        if (row < NN)
            v = h2u(__ldg(&x[(size_t)row * 128 + 2 * kp]),
                    __ldg(&x[(size_t)row * 128 + 2 * kp + 1]));
        *(uint32_t*)(smc + YA + 2 * (m * 136 + 2 * kp)) = v;
    }
    __syncthreads();

    const uint32_t aRow = (uint32_t)((m0 + (lane & 15)) * 136 + ((lane >> 4) << 3)) * 2;
    const uint32_t bRow = (uint32_t)((lane & 7) + ((lane >> 4) << 3));
    const uint32_t bLane = (uint32_t)(bRow * 136 + (((lane >> 3) & 1) << 3)) * 2;

    float acc[8][4];
#pragma unroll
    for (int j = 0; j < 8; ++j)
#pragma unroll
        for (int q = 0; q < 4; ++q) acc[j][q] = 0.f;

#pragma unroll
    for (int ks = 0; ks < 8; ++ks) {
        const uint32_t kOff = (uint32_t)(ks * 16) * 2;
        uint32_t a[4];
        ldsm_x4(a[0], a[1], a[2], a[3], smb + YA + aRow + kOff);
#pragma unroll
        for (int jj = 0; jj < 4; ++jj) {
            const uint32_t nOff = (uint32_t)((nbase + jj * 16) * 136) * 2;
            uint32_t b[4];
            ldsm_x4(b[0], b[1], b[2], b[3], smb + YW + bLane + nOff + kOff);
            mma_f16(acc[2 * jj],     a, b);
            mma_f16(acc[2 * jj + 1], a, b + 2);
        }
    }

    int r0 = m0 + crow, r1 = r0 + 8;
    int nd0 = base + r0, nd1 = base + r1;
#pragma unroll
    for (int j = 0; j < 8; ++j) {
        int c = (nbase + j * 8 + ccol) >> 1;
        if (nd0 < NN) g_yf16[(size_t)nd0 * 64 + c] = h2u(acc[j][0], acc[j][1]);
        if (nd1 < NN) g_yf16[(size_t)nd1 * 64 + c] = h2u(acc[j][2], acc[j][3]);
    }
}

// ================= EDGE KERNEL (factored GEMM1, 3 pipeline groups) =================
#define EK_M   32
#define NT32   (NE / EK_M)
#define NGRP   3
#define LDAT   56          // tail A stride (f16)
#define LDH    136
#define AT_BYTES 3584      // 32*56*2

// smem byte offsets
#define SM_W1T 0           // [128][56] f16 = 14336
#define SM_W2  14336       // [128][136] f16 = 34816
#define SM_H   49152       // 3 * 8704 = 26112
#define SM_A   75264       // 6 * 3584 = 21504  (grp*2+buf)
#define SM_B1  96768
#define SM_B2  97280
#define SM_TGT 97792       // 6 * 32 ints = 768
#define SM_SRC 98560       // 768
#define EDGE_SMEM_BYTES 99328

__device__ __forceinline__ void prefetch_tile(int tile, uint32_t aBase, int* tgtS, int* srcS,
                                              const int* __restrict__ ei, int gt) {
    const int e = gt >> 2, sub = gt & 3;
    const int ge = tile * EK_M + e;
    const char* tf = (const char*)g_tf16 + (size_t)ge * 96;
    const uint32_t arow = aBase + (uint32_t)e * (LDAT * 2);
#pragma unroll
    for (int c = sub; c < 6; c += 4) cp16(arow + c * 16, tf + c * 16);
    if (sub == 0) tgtS[e] = __ldg(&ei[NE + ge]);
    if (sub == 1) srcS[e] = __ldg(&ei[ge]);
}

__global__ __launch_bounds__(384, 1)
void edge_kernel(const float* __restrict__ w1, const float* __restrict__ b1,
                 const float* __restrict__ w2, const float* __restrict__ b2,
                 const int* __restrict__ ei)
{
    extern __shared__ char smc[];
    const uint32_t smb = smem_u32(smc);
    const int tid = threadIdx.x;
    const int wid = tid >> 5, lane = tid & 31;
    const int grp = wid >> 2;            // pipeline group 0..2
    const int gw = wid & 3;              // warp within group (one per SMSP)
    const int nbase = gw * 32;           // 32-col slice per warp
    const int gt = tid & 127;

    float* b1s = (float*)(smc + SM_B1);
    float* b2s = (float*)(smc + SM_B2);

    // ---- stage weights ----
    // W1 tail rows [128:176) -> [n][k] k=0..47
    for (int idx = tid; idx < 48 * DN; idx += 384) {
        int k = idx >> 7, n = idx & 127;
        *(__half*)(smc + SM_W1T + 2 * (n * LDAT + k)) = __float2half_rn(w1[(128 + k) * 128 + n]);
    }
    for (int idx = tid; idx < DN * DN; idx += 384) {
        int k = idx >> 7, n = idx & 127;
        *(__half*)(smc + SM_W2 + 2 * (n * LDH + k)) = __float2half_rn(w2[idx]);
    }
    for (int i = tid; i < 128; i += 384) { b1s[i] = b1[i]; b2s[i] = b2[i]; }
    __syncthreads();

    const int barId = 1 + grp;
    const uint32_t hBase = smb + SM_H + grp * 8704;

    // fragment lane addressing (bytes)
    const uint32_t aRow0T = (uint32_t)((lane & 15) * LDAT + ((lane >> 4) << 3)) * 2;
    const uint32_t aRow1T = aRow0T + (uint32_t)(16 * LDAT) * 2;
    const uint32_t hRow0 = (uint32_t)((lane & 15) * LDH + ((lane >> 4) << 3)) * 2;
    const uint32_t hRow1 = hRow0 + (uint32_t)(16 * LDH) * 2;
    const uint32_t bRow = (uint32_t)((lane & 7) + ((lane >> 4) << 3));
    const uint32_t bColPiece = (uint32_t)(((lane >> 3) & 1) << 3);
    const uint32_t b1LaneOff = (uint32_t)(bRow * LDAT + bColPiece) * 2;
    const uint32_t b2LaneOff = (uint32_t)(bRow * LDH + bColPiece) * 2;
    const int crow = lane >> 2;
    const int ccol = (lane & 3) * 2;

    int buf = 0;
    int tile = blockIdx.x * NGRP + grp;
    const int step = gridDim.x * NGRP;

    if (tile < NT32)
        prefetch_tile(tile, smb + SM_A + (uint32_t)(grp * 2 + buf) * AT_BYTES,
                      (int*)(smc + SM_TGT) + (grp * 2 + buf) * 32,
                      (int*)(smc + SM_SRC) + (grp * 2 + buf) * 32, ei, gt);
    CP_COMMIT();

    for (; tile < NT32; tile += step) {
        const int nxt = tile + step;
        if (nxt < NT32)
            prefetch_tile(nxt, smb + SM_A + (uint32_t)(grp * 2 + (buf ^ 1)) * AT_BYTES,
                          (int*)(smc + SM_TGT) + (grp * 2 + (buf ^ 1)) * 32,
                          (int*)(smc + SM_SRC) + (grp * 2 + (buf ^ 1)) * 32, ei, gt);
        CP_COMMIT();
        CP_WAIT1();
        GBAR(barId);

        const uint32_t aBase = smb + SM_A + (uint32_t)(grp * 2 + buf) * AT_BYTES;
        int* tgts = (int*)(smc + SM_TGT) + (grp * 2 + buf) * 32;
        int* srcs = (int*)(smc + SM_SRC) + (grp * 2 + buf) * 32;

        // ---- issue Y gather early (consumed in epilogue 1) ----
        int s0 = srcs[crow],      s1 = srcs[crow + 8];
        int s2 = srcs[16 + crow], s3 = srcs[24 + crow];
        uint32_t yv[16];
#pragma unroll
        for (int j = 0; j < 4; ++j) {
            int c = (nbase + j * 8 + ccol) >> 1;
            yv[0 * 4 + j] = __ldg(&g_yf16[(size_t)s0 * 64 + c]);
            yv[1 * 4 + j] = __ldg(&g_yf16[(size_t)s1 * 64 + c]);
            yv[2 * 4 + j] = __ldg(&g_yf16[(size_t)s2 * 64 + c]);
            yv[3 * 4 + j] = __ldg(&g_yf16[(size_t)s3 * 64 + c]);
        }

        // acc[mf][piece][quad]
        float acc[2][4][4];
#pragma unroll
        for (int i = 0; i < 2; ++i)
#pragma unroll
            for (int j = 0; j < 4; ++j)
#pragma unroll
                for (int q = 0; q < 4; ++q) acc[i][j][q] = 0.f;

        // ---------- GEMM1': tail[32,48] @ W1t ----------
#pragma unroll
        for (int ks = 0; ks < 3; ++ks) {
            const uint32_t kOff = (uint32_t)(ks * 16) * 2;
            uint32_t a0[4], a1[4];
            ldsm_x4(a0[0], a0[1], a0[2], a0[3], aBase + aRow0T + kOff);
            ldsm_x4(a1[0], a1[1], a1[2], a1[3], aBase + aRow1T + kOff);
#pragma unroll
            for (int jj = 0; jj < 2; ++jj) {
                const uint32_t nOff = (uint32_t)((nbase + jj * 16) * LDAT) * 2;
                uint32_t b[4];
                ldsm_x4(b[0], b[1], b[2], b[3], smb + SM_W1T + b1LaneOff + nOff + kOff);
                mma_f16(acc[0][jj * 2],     a0, b);
                mma_f16(acc[0][jj * 2 + 1], a0, b + 2);
                mma_f16(acc[1][jj * 2],     a1, b);
                mma_f16(acc[1][jj * 2 + 1], a1, b + 2);
            }
        }

        // ---------- epilogue 1: relu(acc + Y + b1) -> H (f16) ----------
#pragma unroll
        for (int mf = 0; mf < 2; ++mf) {
            int r0 = mf * 16 + crow, r1 = r0 + 8;
#pragma unroll
            for (int j = 0; j < 4; ++j) {
                int n = nbase + j * 8 + ccol;
                __half2 y0 = *reinterpret_cast<__half2*>(&yv[(mf * 2 + 0) * 4 + j]);
                __half2 y1 = *reinterpret_cast<__half2*>(&yv[(mf * 2 + 1) * 4 + j]);
                float v0 = fmaxf(acc[mf][j][0] + __low2float(y0)  + b1s[n],     0.f);
                float v1 = fmaxf(acc[mf][j][1] + __high2float(y0) + b1s[n + 1], 0.f);
                float v2 = fmaxf(acc[mf][j][2] + __low2float(y1)  + b1s[n],     0.f);
                float v3 = fmaxf(acc[mf][j][3] + __high2float(y1) + b1s[n + 1], 0.f);
                *(__half2*)(smc + (hBase - smb) + 2 * (r0 * LDH + n)) = __floats2half2_rn(v0, v1);
                *(__half2*)(smc + (hBase - smb) + 2 * (r1 * LDH + n)) = __floats2half2_rn(v2, v3);
            }
        }
        GBAR(barId);

        // ---------- GEMM2: D2 = H(128) @ W2 ----------
#pragma unroll
        for (int i = 0; i < 2; ++i)
#pragma unroll
            for (int j = 0; j < 4; ++j)
#pragma unroll
                for (int q = 0; q < 4; ++q) acc[i][j][q] = 0.f;

#pragma unroll
        for (int ks = 0; ks < 8; ++ks) {
            const uint32_t kOff = (uint32_t)(ks * 16) * 2;
            uint32_t a0[4], a1[4];
            ldsm_x4(a0[0], a0[1], a0[2], a0[3], hBase + hRow0 + kOff);
            ldsm_x4(a1[0], a1[1], a1[2], a1[3], hBase + hRow1 + kOff);
#pragma unroll
            for (int jj = 0; jj < 2; ++jj) {
                const uint32_t nOff = (uint32_t)((nbase + jj * 16) * LDH) * 2;
                uint32_t b[4];
                ldsm_x4(b[0], b[1], b[2], b[3], smb + SM_W2 + b2LaneOff + nOff + kOff);
                mma_f16(acc[0][jj * 2],     a0, b);
                mma_f16(acc[0][jj * 2 + 1], a0, b + 2);
                mma_f16(acc[1][jj * 2],     a1, b);
                mma_f16(acc[1][jj * 2 + 1], a1, b + 2);
            }
        }

        // ---------- epilogue 2: scatter ----------
#pragma unroll
        for (int mf = 0; mf < 2; ++mf) {
            int tg0 = tgts[mf * 16 + crow];
            int tg1 = tgts[mf * 16 + crow + 8];
            size_t ga0 = __cvta_generic_to_global(&g_agg[(size_t)tg0 * 128]);
            size_t ga1 = __cvta_generic_to_global(&g_agg[(size_t)tg1 * 128]);
#pragma unroll
            for (int j = 0; j < 4; ++j) {
                int n = nbase + j * 8 + ccol;
                float v0 = acc[mf][j][0] + b2s[n];
                float v1 = acc[mf][j][1] + b2s[n + 1];
                float v2 = acc[mf][j][2] + b2s[n];
                float v3 = acc[mf][j][3] + b2s[n + 1];
                asm volatile("red.global.add.v2.f32 [%0], {%1,%2};"
                             :: "l"(ga0 + (size_t)n * 4), "f"(v0), "f"(v1) : "memory");
                asm volatile("red.global.add.v2.f32 [%0], {%1,%2};"
                             :: "l"(ga1 + (size_t)n * 4), "f"(v2), "f"(v3) : "memory");
            }
        }
        GBAR(barId);
        buf ^= 1;
    }
}

// ================= NODE KERNEL (unchanged, f16 hybrid hi/lo) =================
#define NLDB 136
#define NB_HI 0
#define NB_LO 34816
#define NVS   69632
#define NMS   87040
#define NODE_SMEM_BYTES 104448

__device__ __forceinline__ void hgemm_128(uint32_t smb, uint32_t aAddr,
                                          uint32_t bHiOff, uint32_t bLoOff,
                                          uint32_t bLaneOff, int nbase, float acc[8][4]) {
#pragma unroll
    for (int j = 0; j < 8; ++j)
#pragma unroll
        for (int q = 0; q < 4; ++q) acc[j][q] = 0.f;
#pragma unroll
    for (int ks = 0; ks < 8; ++ks) {
        const uint32_t kOff = (uint32_t)(ks * 16) * 2;
        uint32_t a[4];
        ldsm_x4(a[0], a[1], a[2], a[3], aAddr + kOff);
#pragma unroll
        for (int jj = 0; jj < 4; ++jj) {
            const uint32_t nOff = (uint32_t)((nbase + jj * 16) * NLDB) * 2;
            uint32_t bh[4], bl[4];
            ldsm_x4(bh[0], bh[1], bh[2], bh[3], smb + bHiOff + bLaneOff + nOff + kOff);
            ldsm_x4(bl[0], bl[1], bl[2], bl[3], smb + bLoOff + bLaneOff + nOff + kOff);
            mma_f16(acc[2 * jj],     a, bh);
            mma_f16(acc[2 * jj + 1], a, bh + 2);
            mma_f16(acc[2 * jj],     a, bl);
            mma_f16(acc[2 * jj + 1], a, bl + 2);
        }
    }
}

__device__ __forceinline__ void node_stageB(char* smc, const float* __restrict__ src, int tid) {
    for (int idx = tid; idx < 128 * 64; idx += 256) {
        int n = idx >> 6, kp = idx & 63;
        float v0 = __ldg(&src[n * 128 + 2 * kp]);
        float v1 = __ldg(&src[n * 128 + 2 * kp + 1]);
        __half h0, l0, h1, l1;
        fsplit(v0, h0, l0);
        fsplit(v1, h1, l1);
        *(__half2*)(smc + NB_HI + 2 * (n * NLDB + 2 * kp)) = __halves2half2(h0, h1);
        *(__half2*)(smc + NB_LO + 2 * (n * NLDB + 2 * kp)) = __halves2half2(l0, l1);
    }
}

__global__ __launch_bounds__(256)
void node_kernel(const float* __restrict__ wih, const float* __restrict__ bih,
                 const float* __restrict__ bhh, const float* __restrict__ ow,
                 const float* __restrict__ ob, float* __restrict__ out)
{
    extern __shared__ char smc[];
    const uint32_t smb = smem_u32(smc);
    const int tid = threadIdx.x, wid = tid >> 5, lane = tid & 31;
    const int m0 = (wid & 3) * 16, nbase = (wid >> 2) * 64;
    const int base = blockIdx.x * 64;
    const int crow = lane >> 2, ccol = (lane & 3) * 2;

    for (int idx = tid; idx < 64 * 64; idx += 256) {
        int m = idx >> 6, kp = idx & 63;
        int nd = base + m;
        float a0 = 0.f, a1 = 0.f;
        if (nd < NN) {
            float inv = 1.0f / fmaxf(g_cnt[nd], 1.0f);
            a0 = g_agg[(size_t)nd * 128 + 2 * kp] * inv;
            a1 = g_agg[(size_t)nd * 128 + 2 * kp + 1] * inv;
        }
        *(__half2*)(smc + NVS + 2 * (m * NLDB + 2 * kp)) = __floats2half2_rn(a0, a1);
    }

    const uint32_t aRow = (uint32_t)((m0 + (lane & 15)) * NLDB + ((lane >> 4) << 3)) * 2;
    const uint32_t bRow = (uint32_t)((lane & 7) + ((lane >> 4) << 3));
    const uint32_t bLane = (uint32_t)(bRow * NLDB + (((lane >> 3) & 1) << 3)) * 2;

    float acc[8][4], rg[8][4], ng[8][4];

    node_stageB(smc, wih, tid);
    __syncthreads();
    hgemm_128(smb, smb + NVS + aRow, NB_HI, NB_LO, bLane, nbase, acc);
#pragma unroll
    for (int j = 0; j < 8; ++j) {
        int n = nbase + j * 8 + ccol;
        rg[j][0] = sigm(acc[j][0] + __ldg(&bih[n])     + __ldg(&bhh[n]));
        rg[j][1] = sigm(acc[j][1] + __ldg(&bih[n + 1]) + __ldg(&bhh[n + 1]));
        rg[j][2] = sigm(acc[j][2] + __ldg(&bih[n])     + __ldg(&bhh[n]));
        rg[j][3] = sigm(acc[j][3] + __ldg(&bih[n + 1]) + __ldg(&bhh[n + 1]));
    }
    __syncthreads();

    node_stageB(smc, wih + 2 * 128 * 128, tid);
    __syncthreads();
    hgemm_128(smb, smb + NVS + aRow, NB_HI, NB_LO, bLane, nbase, acc);
#pragma unroll
    for (int j = 0; j < 8; ++j) {
        int n = 256 + nbase + j * 8 + ccol;
        ng[j][0] = tanhf(acc[j][0] + __ldg(&bih[n])     + rg[j][0] * __ldg(&bhh[n]));
        ng[j][1] = tanhf(acc[j][1] + __ldg(&bih[n + 1]) + rg[j][1] * __ldg(&bhh[n + 1]));
        ng[j][2] = tanhf(acc[j][2] + __ldg(&bih[n])     + rg[j][2] * __ldg(&bhh[n]));
        ng[j][3] = tanhf(acc[j][3] + __ldg(&bih[n + 1]) + rg[j][3] * __ldg(&bhh[n + 1]));
    }
    __syncthreads();

    node_stageB(smc, wih + 1 * 128 * 128, tid);
    __syncthreads();
    hgemm_128(smb, smb + NVS + aRow, NB_HI, NB_LO, bLane, nbase, acc);
    {
        int r0 = m0 + crow, r1 = m0 + crow + 8;
#pragma unroll
        for (int j = 0; j < 8; ++j) {
            int nl = nbase + j * 8 + ccol;
            int n = 128 + nl;
            float z0 = sigm(acc[j][0] + __ldg(&bih[n])     + __ldg(&bhh[n]));
            float z1 = sigm(acc[j][1] + __ldg(&bih[n + 1]) + __ldg(&bhh[n + 1]));
            float z2 = sigm(acc[j][2] + __ldg(&bih[n])     + __ldg(&bhh[n]));
            float z3 = sigm(acc[j][3] + __ldg(&bih[n + 1]) + __ldg(&bhh[n + 1]));
            float m0v = (1.f - z0) * ng[j][0];
            float m1v = (1.f - z1) * ng[j][1];
            float m2v = (1.f - z2) * ng[j][2];
            float m3v = (1.f - z3) * ng[j][3];
            *(__half2*)(smc + NMS + 2 * (r0 * NLDB + nl)) = __floats2half2_rn(m0v, m1v);
            *(__half2*)(smc + NMS + 2 * (r1 * NLDB + nl)) = __floats2half2_rn(m2v, m3v);
        }
    }
    __syncthreads();

    node_stageB(smc, ow, tid);
    __syncthreads();
    hgemm_128(smb, smb + NMS + aRow, NB_HI, NB_LO, bLane, nbase, acc);
    {
        int r0 = m0 + crow, r1 = m0 + crow + 8;
        int nd0 = base + r0, nd1 = base + r1;
#pragma unroll
        for (int j = 0; j < 8; ++j) {
            int n = nbase + j * 8 + ccol;
            float o0 = __ldg(&ob[n]), o1 = __ldg(&ob[n + 1]);
            if (nd0 < NN)
                *(float2*)&out[(size_t)nd0 * 128 + n] = make_float2(acc[j][0] + o0, acc[j][1] + o1);
            if (nd1 < NN)
                *(float2*)&out[(size_t)nd1 * 128 + n] = make_float2(acc[j][2] + o0, acc[j][3] + o1);
        }
    }
}

// ================= launch =================
extern "C" void kernel_launch(void* const* d_in, const int* in_sizes, int n_in,
                              void* d_out, int out_size) {
    const float* x     = (const float*)d_in[0];
    const float* eattr = (const float*)d_in[1];
    const float* t     = (const float*)d_in[2];
    const float* tw    = (const float*)d_in[3];
    const float* tb    = (const float*)d_in[4];
    const float* w1    = (const float*)d_in[5];
    const float* b1    = (const float*)d_in[6];
    const float* w2    = (const float*)d_in[7];
    const float* b2    = (const float*)d_in[8];
    const float* wih   = (const float*)d_in[9];
    const float* bih   = (const float*)d_in[11];
    const float* bhh   = (const float*)d_in[12];
    const float* ow    = (const float*)d_in[13];
    const float* ob    = (const float*)d_in[14];
    const int*   ei    = (const int*)d_in[15];
    float* out = (float*)d_out;

    cudaFuncSetAttribute(edge_kernel, cudaFuncAttributeMaxDynamicSharedMemorySize, EDGE_SMEM_BYTES);
    cudaFuncSetAttribute(node_kernel, cudaFuncAttributeMaxDynamicSharedMemorySize, NODE_SMEM_BYTES);
    cudaFuncSetAttribute(y_kernel,    cudaFuncAttributeMaxDynamicSharedMemorySize, Y_SMEM_BYTES);

    zero_kernel<<<256, 256>>>();
    edge_pre_kernel<<<(NE + 255) / 256, 256>>>(eattr, t, tw, tb, ei);
    y_kernel<<<(NN + 63) / 64, 256, Y_SMEM_BYTES>>>(x, w1);
    edge_kernel<<<148, 384, EDGE_SMEM_BYTES>>>(w1, b1, w2, b2, ei);
    node_kernel<<<(NN + 63) / 64, 256, NODE_SMEM_BYTES>>>(wih, bih, bhh, ow, ob, out);
}